// round 9
// baseline (speedup 1.0000x reference)
#include <cuda_runtime.h>
#include <cuda_bf16.h>
#include <cstdint>

// ---------------------------------------------------------------------------
// Swin shifted-window attention, B=32 H=W=56 C=512 NH=16 HD=32 WS=7 SS=3
//   k0: build row-index table
//   kw: convert weights fp32 -> bf16 hi/lo
//   kx: convert+gather x     -> g_a_hi/lo (bf16, window-row order)
//   k1: QKV GEMM  mma.sync bf16 3-term split, cp.async 3-stage -> g_qkv (fp32)
//   k2: attention per (window, head), vectorized smem -> g_att_hi/lo (bf16)
//   k3: proj GEMM  (scatter-C)                        -> out
// A*B ~= AhiBhi + AhiBlo + AloBhi, fp32 accumulate (rel err ~1e-5).
// tcgen05 unavailable (plain sm_103 target) -> mma.sync m16n8k16 + ldmatrix.
// ---------------------------------------------------------------------------

#define BATCH   32
#define IMG     56
#define CCH     512
#define NHEAD   16
#define HD      32
#define WS      7
#define SS      3
#define NTOK    49
#define TOTWIN  2048
#define MROWS   100352
#define QKVC    1536

// scratch (device globals: allocation-free; NEVER passed from host)
__device__ float g_qkv[(size_t)MROWS * QKVC];
__device__ int   g_rowidx[MROWS];
__device__ __nv_bfloat16 g_a_hi[(size_t)MROWS * CCH];
__device__ __nv_bfloat16 g_a_lo[(size_t)MROWS * CCH];
__device__ __nv_bfloat16 g_att_hi[(size_t)MROWS * CCH];
__device__ __nv_bfloat16 g_att_lo[(size_t)MROWS * CCH];
__device__ __nv_bfloat16 g_wqkv_hi[QKVC * CCH];
__device__ __nv_bfloat16 g_wqkv_lo[QKVC * CCH];
__device__ __nv_bfloat16 g_wp_hi[CCH * CCH];
__device__ __nv_bfloat16 g_wp_lo[CCH * CCH];

__device__ __forceinline__ uint32_t smem_u32(const void* p) {
    uint32_t a;
    asm("{ .reg .u64 t; cvta.to.shared.u64 t, %1; cvt.u32.u64 %0, t; }"
        : "=r"(a) : "l"(p));
    return a;
}
__device__ __forceinline__ uint32_t pack2(__nv_bfloat16 a, __nv_bfloat16 b) {
    return ((uint32_t)__bfloat16_as_ushort(b) << 16) | __bfloat16_as_ushort(a);
}

#define LDSM4(r0, r1, r2, r3, addr)                                            \
    asm volatile("ldmatrix.sync.aligned.m8n8.x4.shared.b16 {%0,%1,%2,%3}, [%4];" \
                 : "=r"(r0), "=r"(r1), "=r"(r2), "=r"(r3) : "r"(addr))

#define MMA_BF16(d, a, b)                                                      \
    asm volatile("mma.sync.aligned.m16n8k16.row.col.f32.bf16.bf16.f32 "        \
                 "{%0,%1,%2,%3}, {%4,%5,%6,%7}, {%8,%9}, {%0,%1,%2,%3};"       \
                 : "+f"((d)[0]), "+f"((d)[1]), "+f"((d)[2]), "+f"((d)[3])      \
                 : "r"((a)[0]), "r"((a)[1]), "r"((a)[2]), "r"((a)[3]),         \
                   "r"((b)[0]), "r"((b)[1]))

__device__ __forceinline__ void cpa16(uint32_t dst, const void* src) {
    asm volatile("cp.async.cg.shared.global [%0], [%1], 16;"
                 :: "r"(dst), "l"(src) : "memory");
}
#define CP_COMMIT() asm volatile("cp.async.commit_group;" ::: "memory")
#define CP_WAIT1()  asm volatile("cp.async.wait_group 1;" ::: "memory")

// ---------------------------------------------------------------------------
__global__ void build_rowidx_kernel() {
    int m = blockIdx.x * 256 + threadIdx.x;
    if (m >= MROWS) return;
    int win = m / NTOK, n = m % NTOK;
    int b  = win >> 6, wi = win & 63;
    int r = (wi >> 3) * WS + n / WS;
    int c = (wi & 7) * WS + n % WS;
    int sh = r + SS; if (sh >= IMG) sh -= IMG;
    int sw = c + SS; if (sw >= IMG) sw -= IMG;
    g_rowidx[m] = (b * IMG + sh) * IMG + sw;
}

__global__ void convert_w_kernel(const float* __restrict__ qkv_w,
                                 const float* __restrict__ proj_w) {
    int i = blockIdx.x * 256 + threadIdx.x;
    if (i < QKVC * CCH) {
        float v = qkv_w[i];
        __nv_bfloat16 h = __float2bfloat16(v);
        g_wqkv_hi[i] = h;
        g_wqkv_lo[i] = __float2bfloat16(v - __bfloat162float(h));
    }
    if (i < CCH * CCH) {
        float v = proj_w[i];
        __nv_bfloat16 h = __float2bfloat16(v);
        g_wp_hi[i] = h;
        g_wp_lo[i] = __float2bfloat16(v - __bfloat162float(h));
    }
}

// gather x through rowidx and split to hi/lo bf16 (window-row order)
__global__ void convert_x_kernel(const float* __restrict__ x) {
    size_t i = (size_t)blockIdx.x * 256 + threadIdx.x;   // over MROWS*128
    if (i >= (size_t)MROWS * 128) return;
    int m = (int)(i >> 7);
    int c4 = (int)(i & 127) << 2;
    float4 v = *(const float4*)(x + (size_t)g_rowidx[m] * CCH + c4);
    __nv_bfloat16 h0 = __float2bfloat16(v.x);
    __nv_bfloat16 h1 = __float2bfloat16(v.y);
    __nv_bfloat16 h2 = __float2bfloat16(v.z);
    __nv_bfloat16 h3 = __float2bfloat16(v.w);
    uint2 hp, lp;
    hp.x = pack2(h0, h1); hp.y = pack2(h2, h3);
    lp.x = pack2(__float2bfloat16(v.x - __bfloat162float(h0)),
                 __float2bfloat16(v.y - __bfloat162float(h1)));
    lp.y = pack2(__float2bfloat16(v.z - __bfloat162float(h2)),
                 __float2bfloat16(v.w - __bfloat162float(h3)));
    size_t o = (size_t)m * CCH + c4;
    *(uint2*)(g_a_hi + o) = hp;
    *(uint2*)(g_a_lo + o) = lp;
}

// ---------------------------------------------------------------------------
// mma.sync GEMM, cp.async 3-stage pipeline.
// BM=BN=128, BK=32, 256 thr (8 warps 4x2, warp tile 32x64).
// Stage buffer (32KB): Ahi/Alo/Bhi/Blo, 128 rows x 64B, chunk-swizzled:
//   phys_chunk = c ^ ((r>>1)&3) ^ ((r>>3)&1)
// ---------------------------------------------------------------------------
#define AHI 0
#define ALO 8192
#define BHI 16384
#define BLO 24576
#define BUFB 32768
#define NSTG 3
#define NKCH 16            // 512/32
#define SMEM_DYN (NSTG * BUFB)

__device__ __forceinline__ uint32_t swz(int r, int c) {
    return (uint32_t)(r * 64 + ((c ^ ((r >> 1) & 3) ^ ((r >> 3) & 1)) << 4));
}

template <bool QKV>
__global__ __launch_bounds__(256)
void gemm_mma_kernel(const float* __restrict__ bias,
                     float* __restrict__ out)
{
    extern __shared__ char smem[];
    const uint32_t sbase = smem_u32(smem);
    const int tid = threadIdx.x;
    const int lane = tid & 31, warp = tid >> 5;
    const int wm = warp >> 1, wn = warp & 1;
    const int bm = blockIdx.y * 128, bn = blockIdx.x * 128;

    const __nv_bfloat16* __restrict__ Ah = QKV ? g_a_hi : g_att_hi;
    const __nv_bfloat16* __restrict__ Al = QKV ? g_a_lo : g_att_lo;
    const __nv_bfloat16* __restrict__ Bh = QKV ? g_wqkv_hi : g_wp_hi;
    const __nv_bfloat16* __restrict__ Bl = QKV ? g_wqkv_lo : g_wp_lo;

    // loader mapping: thread t -> row t/2, k-half t&1 (16 bf16 = 2x16B)
    const int lrow = tid >> 1, half = tid & 1;
    const size_t ga = (size_t)(bm + lrow) * CCH + half * 16;
    const size_t gb = (size_t)(bn + lrow) * CCH + half * 16;
    const uint32_t st0 = swz(lrow, 2 * half);
    const uint32_t st1 = swz(lrow, 2 * half + 1);

    auto issue = [&](int kt, int s) {
        uint32_t b = sbase + s * BUFB;
        const __nv_bfloat16* p;
        p = Ah + ga + kt * 32; cpa16(b + AHI + st0, p); cpa16(b + AHI + st1, p + 8);
        p = Al + ga + kt * 32; cpa16(b + ALO + st0, p); cpa16(b + ALO + st1, p + 8);
        p = Bh + gb + kt * 32; cpa16(b + BHI + st0, p); cpa16(b + BHI + st1, p + 8);
        p = Bl + gb + kt * 32; cpa16(b + BLO + st0, p); cpa16(b + BLO + st1, p + 8);
        CP_COMMIT();
    };

    // per-lane ldmatrix offsets (stage-relative)
    uint32_t aoff[2][2], boff[2][4];
#pragma unroll
    for (int s = 0; s < 2; s++) {
#pragma unroll
        for (int mt = 0; mt < 2; mt++) {
            int r = wm * 32 + mt * 16 + (lane & 15);
            aoff[s][mt] = swz(r, 2 * s + (lane >> 4));
        }
#pragma unroll
        for (int p = 0; p < 4; p++) {
            int n = wn * 64 + p * 16 + ((lane >> 4) & 1) * 8 + (lane & 7);
            boff[s][p] = swz(n, 2 * s + ((lane >> 3) & 1));
        }
    }

    float acc[2][8][4];
#pragma unroll
    for (int mt = 0; mt < 2; mt++)
#pragma unroll
        for (int nt = 0; nt < 8; nt++)
#pragma unroll
            for (int j = 0; j < 4; j++) acc[mt][nt][j] = 0.f;

    auto compute = [&](uint32_t bb) {
#pragma unroll
        for (int s = 0; s < 2; s++) {
            uint32_t ah[2][4], al_[2][4];
#pragma unroll
            for (int mt = 0; mt < 2; mt++) {
                LDSM4(ah[mt][0], ah[mt][1], ah[mt][2], ah[mt][3],
                      bb + AHI + aoff[s][mt]);
                LDSM4(al_[mt][0], al_[mt][1], al_[mt][2], al_[mt][3],
                      bb + ALO + aoff[s][mt]);
            }
            uint32_t bh_[8][2], bl_[8][2];
#pragma unroll
            for (int p = 0; p < 4; p++) {
                uint32_t t0, t1, t2, t3;
                LDSM4(t0, t1, t2, t3, bb + BHI + boff[s][p]);
                bh_[2 * p][0] = t0; bh_[2 * p][1] = t1;
                bh_[2 * p + 1][0] = t2; bh_[2 * p + 1][1] = t3;
                LDSM4(t0, t1, t2, t3, bb + BLO + boff[s][p]);
                bl_[2 * p][0] = t0; bl_[2 * p][1] = t1;
                bl_[2 * p + 1][0] = t2; bl_[2 * p + 1][1] = t3;
            }
#pragma unroll
            for (int mt = 0; mt < 2; mt++)
#pragma unroll
                for (int nt = 0; nt < 8; nt++) {
                    MMA_BF16(acc[mt][nt], ah[mt], bh_[nt]);
                    MMA_BF16(acc[mt][nt], ah[mt], bl_[nt]);
                    MMA_BF16(acc[mt][nt], al_[mt], bh_[nt]);
                }
        }
    };

    // ---- pipeline: 2 chunks in flight ----
    issue(0, 0);
    issue(1, 1);
    for (int kt = 0; kt < NKCH; kt++) {
        CP_WAIT1();                 // chunk kt complete (kt+1 may pend)
        __syncthreads();            // visibility + buffer-reuse ordering
        if (kt + 2 < NKCH) issue(kt + 2, (kt + 2) % NSTG);
        compute(sbase + (kt % NSTG) * BUFB);
    }

    // ---- epilogue: fragment -> global fp32 with bias ----
#pragma unroll
    for (int mt = 0; mt < 2; mt++) {
        int mr = bm + wm * 32 + mt * 16 + (lane >> 2);
        size_t r0, r1;
        if (QKV) { r0 = (size_t)mr * QKVC; r1 = (size_t)(mr + 8) * QKVC; }
        else     { r0 = (size_t)g_rowidx[mr] * CCH;
                   r1 = (size_t)g_rowidx[mr + 8] * CCH; }
        float* bp = QKV ? g_qkv : out;
        const int cbase = bn + wn * 64 + 2 * (lane & 3);
        float* p0 = bp + r0 + cbase;
        float* p1 = bp + r1 + cbase;
#pragma unroll
        for (int nt = 0; nt < 8; nt++) {
            float2 bb = *(const float2*)(bias + cbase + nt * 8);
            float2 v0, v1;
            v0.x = acc[mt][nt][0] + bb.x; v0.y = acc[mt][nt][1] + bb.y;
            v1.x = acc[mt][nt][2] + bb.x; v1.y = acc[mt][nt][3] + bb.y;
            *(float2*)(p0 + nt * 8) = v0;
            *(float2*)(p1 + nt * 8) = v1;
        }
    }
}

// ---------------------------------------------------------------------------
// Attention: one block per (window, head). 256 threads.
// Row stride 36 floats (144B = 9x16B): float4 LDS everywhere, conflict-free.
// Output written as bf16 hi/lo (consumed by the proj GEMM split).
// ---------------------------------------------------------------------------
#define QKS 36

__global__ __launch_bounds__(256)
void attn_kernel(const float* __restrict__ rel)
{
    const int win = blockIdx.x >> 4;
    const int h   = blockIdx.x & 15;
    const int tid = threadIdx.x;

    __shared__ __align__(16) float qs[NTOK * QKS];
    __shared__ __align__(16) float ks[NTOK * QKS];
    __shared__ __align__(16) float vs[NTOK * QKS];
    __shared__ float S[NTOK][50];
    __shared__ float tb[169];
    __shared__ int   lab[NTOK];

    const float scale = 0.17677669529663687f;
    const size_t base = (size_t)win * NTOK * QKVC + h * HD;

    for (int e = tid; e < NTOK * 8; e += 256) {
        int n = e >> 3, c4 = (e & 7) * 4;
        const float* p = g_qkv + base + (size_t)n * QKVC + c4;
        float4 q4 = *(const float4*)(p);
        float4 k4 = *(const float4*)(p + 512);
        float4 v4 = *(const float4*)(p + 1024);
        q4.x *= scale; q4.y *= scale; q4.z *= scale; q4.w *= scale;
        *(float4*)&qs[n * QKS + c4] = q4;
        *(float4*)&ks[n * QKS + c4] = k4;
        *(float4*)&vs[n * QKS + c4] = v4;
    }
    if (tid < 169) tb[tid] = rel[tid * NHEAD + h];
    if (tid < NTOK) {
        int wi = win & 63;
        int r = (wi >> 3) * WS + tid / WS;
        int c = (wi & 7) * WS + tid % WS;
        int rh = (r < IMG - WS) ? 0 : (r < IMG - SS ? 1 : 2);
        int rw = (c < IMG - WS) ? 0 : (c < IMG - SS ? 1 : 2);
        lab[tid] = rh * 3 + rw;
    }
    __syncthreads();

    // scores + bias + mask  (float4 over d: 2 LDS.128 per 4 FMA)
    for (int e = tid; e < NTOK * NTOK; e += 256) {
        int n = (e * 1338) >> 16;          // e/49 for e<2401
        int mm = e - n * NTOK;
        const float* qp = &qs[n * QKS];
        const float* kp = &ks[mm * QKS];
        float a = 0.f;
#pragma unroll
        for (int d4 = 0; d4 < 8; d4++) {
            float4 q = *(const float4*)(qp + d4 * 4);
            float4 k = *(const float4*)(kp + d4 * 4);
            a = fmaf(q.x, k.x, a); a = fmaf(q.y, k.y, a);
            a = fmaf(q.z, k.z, a); a = fmaf(q.w, k.w, a);
        }
        int dr = n / WS - mm / WS + (WS - 1);
        int dc = n % WS - mm % WS + (WS - 1);
        a += tb[dr * (2 * WS - 1) + dc];
        if (lab[n] != lab[mm]) a -= 100.0f;
        S[n][mm] = a;
    }
    __syncthreads();

    // row softmax: warp per row (strided)
    const int warp = tid >> 5, lane = tid & 31;
    for (int n = warp; n < NTOK; n += 8) {
        float v0 = (lane < NTOK)      ? S[n][lane]      : -1e30f;
        float v1 = (lane + 32 < NTOK) ? S[n][lane + 32] : -1e30f;
        float mx = fmaxf(v0, v1);
#pragma unroll
        for (int o = 16; o > 0; o >>= 1)
            mx = fmaxf(mx, __shfl_xor_sync(0xffffffffu, mx, o));
        float e0 = (lane < NTOK)      ? __expf(v0 - mx) : 0.f;
        float e1 = (lane + 32 < NTOK) ? __expf(v1 - mx) : 0.f;
        float sm = e0 + e1;
#pragma unroll
        for (int o = 16; o > 0; o >>= 1)
            sm += __shfl_xor_sync(0xffffffffu, sm, o);
        float inv = 1.0f / sm;
        if (lane < NTOK)      S[n][lane]      = e0 * inv;
        if (lane + 32 < NTOK) S[n][lane + 32] = e1 * inv;
    }
    __syncthreads();

    // out = P @ V -> bf16 hi/lo  (thread = (n, 4 consecutive d))
    const size_t obase = (size_t)win * NTOK * CCH + h * HD;
    for (int e = tid; e < NTOK * 8; e += 256) {
        int n = e >> 3, d4 = (e & 7) * 4;
        float ax = 0.f, ay = 0.f, az = 0.f, aw = 0.f;
#pragma unroll
        for (int mm = 0; mm < NTOK; mm++) {
            float s = S[n][mm];
            float4 v = *(const float4*)&vs[mm * QKS + d4];
            ax = fmaf(s, v.x, ax); ay = fmaf(s, v.y, ay);
            az = fmaf(s, v.z, az); aw = fmaf(s, v.w, aw);
        }
        __nv_bfloat16 h0 = __float2bfloat16(ax);
        __nv_bfloat16 h1 = __float2bfloat16(ay);
        __nv_bfloat16 h2 = __float2bfloat16(az);
        __nv_bfloat16 h3 = __float2bfloat16(aw);
        uint2 hp, lp;
        hp.x = pack2(h0, h1); hp.y = pack2(h2, h3);
        lp.x = pack2(__float2bfloat16(ax - __bfloat162float(h0)),
                     __float2bfloat16(ay - __bfloat162float(h1)));
        lp.y = pack2(__float2bfloat16(az - __bfloat162float(h2)),
                     __float2bfloat16(aw - __bfloat162float(h3)));
        size_t o = obase + (size_t)n * CCH + d4;
        *(uint2*)(g_att_hi + o) = hp;
        *(uint2*)(g_att_lo + o) = lp;
    }
}

// ---------------------------------------------------------------------------
extern "C" void kernel_launch(void* const* d_in, const int* in_sizes, int n_in,
                              void* d_out, int out_size)
{
    const float* x      = (const float*)d_in[0];
    const float* qkv_w  = (const float*)d_in[1];
    const float* qkv_b  = (const float*)d_in[2];
    const float* proj_w = (const float*)d_in[3];
    const float* proj_b = (const float*)d_in[4];
    const float* rel    = (const float*)d_in[5];
    float* out = (float*)d_out;

    cudaFuncSetAttribute(gemm_mma_kernel<true>,
                         cudaFuncAttributeMaxDynamicSharedMemorySize, SMEM_DYN);
    cudaFuncSetAttribute(gemm_mma_kernel<false>,
                         cudaFuncAttributeMaxDynamicSharedMemorySize, SMEM_DYN);

    build_rowidx_kernel<<<(MROWS + 255) / 256, 256>>>();
    convert_w_kernel<<<(QKVC * CCH + 255) / 256, 256>>>(qkv_w, proj_w);
    convert_x_kernel<<<(int)(((size_t)MROWS * 128 + 255) / 256), 256>>>(x);

    // QKV: M=100352, N=1536
    gemm_mma_kernel<true><<<dim3(QKVC / 128, MROWS / 128), 256, SMEM_DYN>>>(
        qkv_b, nullptr);

    attn_kernel<<<TOTWIN * NHEAD, 256>>>(rel);

    // proj: M=100352, N=512 (A = g_att_hi/lo in-kernel, scatter-C to out)
    gemm_mma_kernel<false><<<dim3(CCH / 128, MROWS / 128), 256, SMEM_DYN>>>(
        proj_b, out);
}

// round 10
// speedup vs baseline: 1.0884x; 1.0884x over previous
#include <cuda_runtime.h>
#include <cuda_bf16.h>
#include <cstdint>

// ---------------------------------------------------------------------------
// Swin shifted-window attention, B=32 H=W=56 C=512 NH=16 HD=32 WS=7 SS=3
//   k0: build row-index table
//   kw: convert weights fp32 -> bf16 hi/lo
//   kx: convert+gather x     -> g_a_hi/lo (bf16, window-row order)
//   k1: QKV GEMM  mma.sync bf16 3-term split, cp.async 3-stage -> g_qkv (fp32)
//   k2: attention per (window, head), vectorized smem -> g_att_hi/lo (bf16)
//   k3: proj GEMM  (scatter-C)                        -> out
// A*B ~= AhiBhi + AhiBlo + AloBhi, fp32 accumulate (rel err ~1e-5).
// tcgen05 unavailable (plain sm_103 target) -> mma.sync m16n8k16 + ldmatrix.
//
// R9 -> R10: GEMM was 1 CTA/SM (regs=129, occ=12.3%, tensor=51.5%).
// __launch_bounds__(256,2) caps regs at 128 -> 2 CTAs/SM; B loads use
// cp.async.ca (L1-cached, B shared across all M-blocks).
// ---------------------------------------------------------------------------

#define BATCH   32
#define IMG     56
#define CCH     512
#define NHEAD   16
#define HD      32
#define WS      7
#define SS      3
#define NTOK    49
#define TOTWIN  2048
#define MROWS   100352
#define QKVC    1536

// scratch (device globals: allocation-free; NEVER passed from host)
__device__ float g_qkv[(size_t)MROWS * QKVC];
__device__ int   g_rowidx[MROWS];
__device__ __nv_bfloat16 g_a_hi[(size_t)MROWS * CCH];
__device__ __nv_bfloat16 g_a_lo[(size_t)MROWS * CCH];
__device__ __nv_bfloat16 g_att_hi[(size_t)MROWS * CCH];
__device__ __nv_bfloat16 g_att_lo[(size_t)MROWS * CCH];
__device__ __nv_bfloat16 g_wqkv_hi[QKVC * CCH];
__device__ __nv_bfloat16 g_wqkv_lo[QKVC * CCH];
__device__ __nv_bfloat16 g_wp_hi[CCH * CCH];
__device__ __nv_bfloat16 g_wp_lo[CCH * CCH];

__device__ __forceinline__ uint32_t smem_u32(const void* p) {
    uint32_t a;
    asm("{ .reg .u64 t; cvta.to.shared.u64 t, %1; cvt.u32.u64 %0, t; }"
        : "=r"(a) : "l"(p));
    return a;
}
__device__ __forceinline__ uint32_t pack2(__nv_bfloat16 a, __nv_bfloat16 b) {
    return ((uint32_t)__bfloat16_as_ushort(b) << 16) | __bfloat16_as_ushort(a);
}

#define LDSM4(r0, r1, r2, r3, addr)                                            \
    asm volatile("ldmatrix.sync.aligned.m8n8.x4.shared.b16 {%0,%1,%2,%3}, [%4];" \
                 : "=r"(r0), "=r"(r1), "=r"(r2), "=r"(r3) : "r"(addr))

#define MMA_BF16(d, a, b)                                                      \
    asm volatile("mma.sync.aligned.m16n8k16.row.col.f32.bf16.bf16.f32 "        \
                 "{%0,%1,%2,%3}, {%4,%5,%6,%7}, {%8,%9}, {%0,%1,%2,%3};"       \
                 : "+f"((d)[0]), "+f"((d)[1]), "+f"((d)[2]), "+f"((d)[3])      \
                 : "r"((a)[0]), "r"((a)[1]), "r"((a)[2]), "r"((a)[3]),         \
                   "r"((b)[0]), "r"((b)[1]))

__device__ __forceinline__ void cpa16_cg(uint32_t dst, const void* src) {
    asm volatile("cp.async.cg.shared.global [%0], [%1], 16;"
                 :: "r"(dst), "l"(src) : "memory");
}
__device__ __forceinline__ void cpa16_ca(uint32_t dst, const void* src) {
    asm volatile("cp.async.ca.shared.global [%0], [%1], 16;"
                 :: "r"(dst), "l"(src) : "memory");
}
#define CP_COMMIT() asm volatile("cp.async.commit_group;" ::: "memory")
#define CP_WAIT1()  asm volatile("cp.async.wait_group 1;" ::: "memory")

// ---------------------------------------------------------------------------
__global__ void build_rowidx_kernel() {
    int m = blockIdx.x * 256 + threadIdx.x;
    if (m >= MROWS) return;
    int win = m / NTOK, n = m % NTOK;
    int b  = win >> 6, wi = win & 63;
    int r = (wi >> 3) * WS + n / WS;
    int c = (wi & 7) * WS + n % WS;
    int sh = r + SS; if (sh >= IMG) sh -= IMG;
    int sw = c + SS; if (sw >= IMG) sw -= IMG;
    g_rowidx[m] = (b * IMG + sh) * IMG + sw;
}

__global__ void convert_w_kernel(const float* __restrict__ qkv_w,
                                 const float* __restrict__ proj_w) {
    int i = blockIdx.x * 256 + threadIdx.x;
    if (i < QKVC * CCH) {
        float v = qkv_w[i];
        __nv_bfloat16 h = __float2bfloat16(v);
        g_wqkv_hi[i] = h;
        g_wqkv_lo[i] = __float2bfloat16(v - __bfloat162float(h));
    }
    if (i < CCH * CCH) {
        float v = proj_w[i];
        __nv_bfloat16 h = __float2bfloat16(v);
        g_wp_hi[i] = h;
        g_wp_lo[i] = __float2bfloat16(v - __bfloat162float(h));
    }
}

// gather x through rowidx and split to hi/lo bf16 (window-row order)
__global__ void convert_x_kernel(const float* __restrict__ x) {
    size_t i = (size_t)blockIdx.x * 256 + threadIdx.x;   // over MROWS*128
    if (i >= (size_t)MROWS * 128) return;
    int m = (int)(i >> 7);
    int c4 = (int)(i & 127) << 2;
    float4 v = *(const float4*)(x + (size_t)g_rowidx[m] * CCH + c4);
    __nv_bfloat16 h0 = __float2bfloat16(v.x);
    __nv_bfloat16 h1 = __float2bfloat16(v.y);
    __nv_bfloat16 h2 = __float2bfloat16(v.z);
    __nv_bfloat16 h3 = __float2bfloat16(v.w);
    uint2 hp, lp;
    hp.x = pack2(h0, h1); hp.y = pack2(h2, h3);
    lp.x = pack2(__float2bfloat16(v.x - __bfloat162float(h0)),
                 __float2bfloat16(v.y - __bfloat162float(h1)));
    lp.y = pack2(__float2bfloat16(v.z - __bfloat162float(h2)),
                 __float2bfloat16(v.w - __bfloat162float(h3)));
    size_t o = (size_t)m * CCH + c4;
    *(uint2*)(g_a_hi + o) = hp;
    *(uint2*)(g_a_lo + o) = lp;
}

// ---------------------------------------------------------------------------
// mma.sync GEMM, cp.async 3-stage pipeline, 2 CTAs/SM.
// BM=BN=128, BK=32, 256 thr (8 warps 4x2, warp tile 32x64).
// Stage buffer (32KB): Ahi/Alo/Bhi/Blo, 128 rows x 64B, chunk-swizzled:
//   phys_chunk = c ^ ((r>>1)&3) ^ ((r>>3)&1)
// ---------------------------------------------------------------------------
#define AHI 0
#define ALO 8192
#define BHI 16384
#define BLO 24576
#define BUFB 32768
#define NSTG 3
#define NKCH 16            // 512/32
#define SMEM_DYN (NSTG * BUFB)

__device__ __forceinline__ uint32_t swz(int r, int c) {
    return (uint32_t)(r * 64 + ((c ^ ((r >> 1) & 3) ^ ((r >> 3) & 1)) << 4));
}

template <bool QKV>
__global__ __launch_bounds__(256, 2)
void gemm_mma_kernel(const float* __restrict__ bias,
                     float* __restrict__ out)
{
    extern __shared__ char smem[];
    const uint32_t sbase = smem_u32(smem);
    const int tid = threadIdx.x;
    const int lane = tid & 31, warp = tid >> 5;
    const int wm = warp >> 1, wn = warp & 1;
    const int bm = blockIdx.y * 128, bn = blockIdx.x * 128;

    const __nv_bfloat16* __restrict__ Ah = QKV ? g_a_hi : g_att_hi;
    const __nv_bfloat16* __restrict__ Al = QKV ? g_a_lo : g_att_lo;
    const __nv_bfloat16* __restrict__ Bh = QKV ? g_wqkv_hi : g_wp_hi;
    const __nv_bfloat16* __restrict__ Bl = QKV ? g_wqkv_lo : g_wp_lo;

    // loader mapping: thread t -> row t/2, k-half t&1 (16 bf16 = 2x16B)
    const int lrow = tid >> 1, half = tid & 1;
    const size_t ga = (size_t)(bm + lrow) * CCH + half * 16;
    const size_t gb = (size_t)(bn + lrow) * CCH + half * 16;
    const uint32_t st0 = swz(lrow, 2 * half);
    const uint32_t st1 = swz(lrow, 2 * half + 1);

    auto issue = [&](int kt, int s) {
        uint32_t b = sbase + s * BUFB;
        const __nv_bfloat16* p;
        p = Ah + ga + kt * 32; cpa16_cg(b + AHI + st0, p); cpa16_cg(b + AHI + st1, p + 8);
        p = Al + ga + kt * 32; cpa16_cg(b + ALO + st0, p); cpa16_cg(b + ALO + st1, p + 8);
        p = Bh + gb + kt * 32; cpa16_ca(b + BHI + st0, p); cpa16_ca(b + BHI + st1, p + 8);
        p = Bl + gb + kt * 32; cpa16_ca(b + BLO + st0, p); cpa16_ca(b + BLO + st1, p + 8);
        CP_COMMIT();
    };

    // per-lane ldmatrix offsets (stage-relative)
    uint32_t aoff[2][2], boff[2][4];
#pragma unroll
    for (int s = 0; s < 2; s++) {
#pragma unroll
        for (int mt = 0; mt < 2; mt++) {
            int r = wm * 32 + mt * 16 + (lane & 15);
            aoff[s][mt] = swz(r, 2 * s + (lane >> 4));
        }
#pragma unroll
        for (int p = 0; p < 4; p++) {
            int n = wn * 64 + p * 16 + ((lane >> 4) & 1) * 8 + (lane & 7);
            boff[s][p] = swz(n, 2 * s + ((lane >> 3) & 1));
        }
    }

    float acc[2][8][4];
#pragma unroll
    for (int mt = 0; mt < 2; mt++)
#pragma unroll
        for (int nt = 0; nt < 8; nt++)
#pragma unroll
            for (int j = 0; j < 4; j++) acc[mt][nt][j] = 0.f;

    auto compute = [&](uint32_t bb) {
#pragma unroll
        for (int s = 0; s < 2; s++) {
            uint32_t ah[2][4], al_[2][4];
#pragma unroll
            for (int mt = 0; mt < 2; mt++) {
                LDSM4(ah[mt][0], ah[mt][1], ah[mt][2], ah[mt][3],
                      bb + AHI + aoff[s][mt]);
                LDSM4(al_[mt][0], al_[mt][1], al_[mt][2], al_[mt][3],
                      bb + ALO + aoff[s][mt]);
            }
            uint32_t bh_[8][2], bl_[8][2];
#pragma unroll
            for (int p = 0; p < 4; p++) {
                uint32_t t0, t1, t2, t3;
                LDSM4(t0, t1, t2, t3, bb + BHI + boff[s][p]);
                bh_[2 * p][0] = t0; bh_[2 * p][1] = t1;
                bh_[2 * p + 1][0] = t2; bh_[2 * p + 1][1] = t3;
                LDSM4(t0, t1, t2, t3, bb + BLO + boff[s][p]);
                bl_[2 * p][0] = t0; bl_[2 * p][1] = t1;
                bl_[2 * p + 1][0] = t2; bl_[2 * p + 1][1] = t3;
            }
#pragma unroll
            for (int mt = 0; mt < 2; mt++)
#pragma unroll
                for (int nt = 0; nt < 8; nt++) {
                    MMA_BF16(acc[mt][nt], ah[mt], bh_[nt]);
                    MMA_BF16(acc[mt][nt], ah[mt], bl_[nt]);
                    MMA_BF16(acc[mt][nt], al_[mt], bh_[nt]);
                }
        }
    };

    // ---- pipeline: 2 chunks in flight ----
    issue(0, 0);
    issue(1, 1);
    for (int kt = 0; kt < NKCH; kt++) {
        CP_WAIT1();                 // chunk kt complete (kt+1 may pend)
        __syncthreads();            // visibility + buffer-reuse ordering
        if (kt + 2 < NKCH) issue(kt + 2, (kt + 2) % NSTG);
        compute(sbase + (kt % NSTG) * BUFB);
    }

    // ---- epilogue: fragment -> global fp32 with bias ----
#pragma unroll
    for (int mt = 0; mt < 2; mt++) {
        int mr = bm + wm * 32 + mt * 16 + (lane >> 2);
        size_t r0, r1;
        if (QKV) { r0 = (size_t)mr * QKVC; r1 = (size_t)(mr + 8) * QKVC; }
        else     { r0 = (size_t)g_rowidx[mr] * CCH;
                   r1 = (size_t)g_rowidx[mr + 8] * CCH; }
        float* bp = QKV ? g_qkv : out;
        const int cbase = bn + wn * 64 + 2 * (lane & 3);
        float* p0 = bp + r0 + cbase;
        float* p1 = bp + r1 + cbase;
#pragma unroll
        for (int nt = 0; nt < 8; nt++) {
            float2 bb = *(const float2*)(bias + cbase + nt * 8);
            float2 v0, v1;
            v0.x = acc[mt][nt][0] + bb.x; v0.y = acc[mt][nt][1] + bb.y;
            v1.x = acc[mt][nt][2] + bb.x; v1.y = acc[mt][nt][3] + bb.y;
            *(float2*)(p0 + nt * 8) = v0;
            *(float2*)(p1 + nt * 8) = v1;
        }
    }
}

// ---------------------------------------------------------------------------
// Attention: one block per (window, head). 256 threads.
// Row stride 36 floats (144B = 9x16B): float4 LDS everywhere, conflict-free.
// Output written as bf16 hi/lo (consumed by the proj GEMM split).
// ---------------------------------------------------------------------------
#define QKS 36

__global__ __launch_bounds__(256)
void attn_kernel(const float* __restrict__ rel)
{
    const int win = blockIdx.x >> 4;
    const int h   = blockIdx.x & 15;
    const int tid = threadIdx.x;

    __shared__ __align__(16) float qs[NTOK * QKS];
    __shared__ __align__(16) float ks[NTOK * QKS];
    __shared__ __align__(16) float vs[NTOK * QKS];
    __shared__ float S[NTOK][50];
    __shared__ float tb[169];
    __shared__ int   lab[NTOK];

    const float scale = 0.17677669529663687f;
    const size_t base = (size_t)win * NTOK * QKVC + h * HD;

    for (int e = tid; e < NTOK * 8; e += 256) {
        int n = e >> 3, c4 = (e & 7) * 4;
        const float* p = g_qkv + base + (size_t)n * QKVC + c4;
        float4 q4 = *(const float4*)(p);
        float4 k4 = *(const float4*)(p + 512);
        float4 v4 = *(const float4*)(p + 1024);
        q4.x *= scale; q4.y *= scale; q4.z *= scale; q4.w *= scale;
        *(float4*)&qs[n * QKS + c4] = q4;
        *(float4*)&ks[n * QKS + c4] = k4;
        *(float4*)&vs[n * QKS + c4] = v4;
    }
    if (tid < 169) tb[tid] = rel[tid * NHEAD + h];
    if (tid < NTOK) {
        int wi = win & 63;
        int r = (wi >> 3) * WS + tid / WS;
        int c = (wi & 7) * WS + tid % WS;
        int rh = (r < IMG - WS) ? 0 : (r < IMG - SS ? 1 : 2);
        int rw = (c < IMG - WS) ? 0 : (c < IMG - SS ? 1 : 2);
        lab[tid] = rh * 3 + rw;
    }
    __syncthreads();

    // scores + bias + mask  (float4 over d: 2 LDS.128 per 4 FMA)
    for (int e = tid; e < NTOK * NTOK; e += 256) {
        int n = (e * 1338) >> 16;          // e/49 for e<2401
        int mm = e - n * NTOK;
        const float* qp = &qs[n * QKS];
        const float* kp = &ks[mm * QKS];
        float a = 0.f;
#pragma unroll
        for (int d4 = 0; d4 < 8; d4++) {
            float4 q = *(const float4*)(qp + d4 * 4);
            float4 k = *(const float4*)(kp + d4 * 4);
            a = fmaf(q.x, k.x, a); a = fmaf(q.y, k.y, a);
            a = fmaf(q.z, k.z, a); a = fmaf(q.w, k.w, a);
        }
        int dr = n / WS - mm / WS + (WS - 1);
        int dc = n % WS - mm % WS + (WS - 1);
        a += tb[dr * (2 * WS - 1) + dc];
        if (lab[n] != lab[mm]) a -= 100.0f;
        S[n][mm] = a;
    }
    __syncthreads();

    // row softmax: warp per row (strided)
    const int warp = tid >> 5, lane = tid & 31;
    for (int n = warp; n < NTOK; n += 8) {
        float v0 = (lane < NTOK)      ? S[n][lane]      : -1e30f;
        float v1 = (lane + 32 < NTOK) ? S[n][lane + 32] : -1e30f;
        float mx = fmaxf(v0, v1);
#pragma unroll
        for (int o = 16; o > 0; o >>= 1)
            mx = fmaxf(mx, __shfl_xor_sync(0xffffffffu, mx, o));
        float e0 = (lane < NTOK)      ? __expf(v0 - mx) : 0.f;
        float e1 = (lane + 32 < NTOK) ? __expf(v1 - mx) : 0.f;
        float sm = e0 + e1;
#pragma unroll
        for (int o = 16; o > 0; o >>= 1)
            sm += __shfl_xor_sync(0xffffffffu, sm, o);
        float inv = 1.0f / sm;
        if (lane < NTOK)      S[n][lane]      = e0 * inv;
        if (lane + 32 < NTOK) S[n][lane + 32] = e1 * inv;
    }
    __syncthreads();

    // out = P @ V -> bf16 hi/lo  (thread = (n, 4 consecutive d))
    const size_t obase = (size_t)win * NTOK * CCH + h * HD;
    for (int e = tid; e < NTOK * 8; e += 256) {
        int n = e >> 3, d4 = (e & 7) * 4;
        float ax = 0.f, ay = 0.f, az = 0.f, aw = 0.f;
#pragma unroll
        for (int mm = 0; mm < NTOK; mm++) {
            float s = S[n][mm];
            float4 v = *(const float4*)&vs[mm * QKS + d4];
            ax = fmaf(s, v.x, ax); ay = fmaf(s, v.y, ay);
            az = fmaf(s, v.z, az); aw = fmaf(s, v.w, aw);
        }
        __nv_bfloat16 h0 = __float2bfloat16(ax);
        __nv_bfloat16 h1 = __float2bfloat16(ay);
        __nv_bfloat16 h2 = __float2bfloat16(az);
        __nv_bfloat16 h3 = __float2bfloat16(aw);
        uint2 hp, lp;
        hp.x = pack2(h0, h1); hp.y = pack2(h2, h3);
        lp.x = pack2(__float2bfloat16(ax - __bfloat162float(h0)),
                     __float2bfloat16(ay - __bfloat162float(h1)));
        lp.y = pack2(__float2bfloat16(az - __bfloat162float(h2)),
                     __float2bfloat16(aw - __bfloat162float(h3)));
        size_t o = obase + (size_t)n * CCH + d4;
        *(uint2*)(g_att_hi + o) = hp;
        *(uint2*)(g_att_lo + o) = lp;
    }
}

// ---------------------------------------------------------------------------
extern "C" void kernel_launch(void* const* d_in, const int* in_sizes, int n_in,
                              void* d_out, int out_size)
{
    const float* x      = (const float*)d_in[0];
    const float* qkv_w  = (const float*)d_in[1];
    const float* qkv_b  = (const float*)d_in[2];
    const float* proj_w = (const float*)d_in[3];
    const float* proj_b = (const float*)d_in[4];
    const float* rel    = (const float*)d_in[5];
    float* out = (float*)d_out;

    cudaFuncSetAttribute(gemm_mma_kernel<true>,
                         cudaFuncAttributeMaxDynamicSharedMemorySize, SMEM_DYN);
    cudaFuncSetAttribute(gemm_mma_kernel<false>,
                         cudaFuncAttributeMaxDynamicSharedMemorySize, SMEM_DYN);

    build_rowidx_kernel<<<(MROWS + 255) / 256, 256>>>();
    convert_w_kernel<<<(QKVC * CCH + 255) / 256, 256>>>(qkv_w, proj_w);
    convert_x_kernel<<<(int)(((size_t)MROWS * 128 + 255) / 256), 256>>>(x);

    // QKV: M=100352, N=1536
    gemm_mma_kernel<true><<<dim3(QKVC / 128, MROWS / 128), 256, SMEM_DYN>>>(
        qkv_b, nullptr);

    attn_kernel<<<TOTWIN * NHEAD, 256>>>(rel);

    // proj: M=100352, N=512 (A = g_att_hi/lo in-kernel, scatter-C to out)
    gemm_mma_kernel<false><<<dim3(CCH / 128, MROWS / 128), 256, SMEM_DYN>>>(
        proj_b, out);
}

// round 11
// speedup vs baseline: 1.2739x; 1.1705x over previous
#include <cuda_runtime.h>
#include <cuda_bf16.h>
#include <cuda_fp16.h>
#include <cstdint>

// ---------------------------------------------------------------------------
// Swin shifted-window attention, B=32 H=W=56 C=512 NH=16 HD=32 WS=7 SS=3
//   k0: build row-index table
//   kw: convert weights fp32 -> fp16 (single)
//   kx: convert+gather x     -> g_a_hi/lo (fp16 pair, window-row order)
//   k1: QKV GEMM  mma.sync fp16 2-term split, cp.async 4-stage -> g_qkv (fp32)
//   k2: attention per (window, head) -> g_att_hi/lo (fp16 pair)
//   k3: proj GEMM (scatter-C)        -> out
//
// Precision: A = Ahi + Alo exactly (fp16 pair, ~2^-21); B = fp16(W) (~2^-12).
// C = Ahi*B + Alo*B, fp32 accumulate. Per-stage rel err ~1.4e-4; total ~3e-4.
// This cuts executed MMAs from 3 terms to 2 and smem tiles from 4 to 3
// vs the bf16 3-term scheme (R10: tensor=60%, L1=63% -> MMA-work-bound).
// tcgen05 unavailable (plain sm_103 ptxas target) -> mma.sync + ldmatrix.
// ---------------------------------------------------------------------------

#define BATCH   32
#define IMG     56
#define CCH     512
#define NHEAD   16
#define HD      32
#define WS      7
#define SS      3
#define NTOK    49
#define TOTWIN  2048
#define MROWS   100352
#define QKVC    1536

// scratch (device globals: allocation-free; NEVER passed from host)
__device__ float g_qkv[(size_t)MROWS * QKVC];
__device__ int   g_rowidx[MROWS];
__device__ __half g_a_hi[(size_t)MROWS * CCH];
__device__ __half g_a_lo[(size_t)MROWS * CCH];
__device__ __half g_att_hi[(size_t)MROWS * CCH];
__device__ __half g_att_lo[(size_t)MROWS * CCH];
__device__ __half g_wqkv_h[QKVC * CCH];
__device__ __half g_wp_h[CCH * CCH];

__device__ __forceinline__ uint32_t smem_u32(const void* p) {
    uint32_t a;
    asm("{ .reg .u64 t; cvta.to.shared.u64 t, %1; cvt.u32.u64 %0, t; }"
        : "=r"(a) : "l"(p));
    return a;
}
__device__ __forceinline__ uint32_t pack2h(__half a, __half b) {
    return ((uint32_t)__half_as_ushort(b) << 16) | __half_as_ushort(a);
}

#define LDSM4(r0, r1, r2, r3, addr)                                            \
    asm volatile("ldmatrix.sync.aligned.m8n8.x4.shared.b16 {%0,%1,%2,%3}, [%4];" \
                 : "=r"(r0), "=r"(r1), "=r"(r2), "=r"(r3) : "r"(addr))

#define MMA_FP16(d, a, b)                                                      \
    asm volatile("mma.sync.aligned.m16n8k16.row.col.f32.f16.f16.f32 "          \
                 "{%0,%1,%2,%3}, {%4,%5,%6,%7}, {%8,%9}, {%0,%1,%2,%3};"       \
                 : "+f"((d)[0]), "+f"((d)[1]), "+f"((d)[2]), "+f"((d)[3])      \
                 : "r"((a)[0]), "r"((a)[1]), "r"((a)[2]), "r"((a)[3]),         \
                   "r"((b)[0]), "r"((b)[1]))

__device__ __forceinline__ void cpa16_cg(uint32_t dst, const void* src) {
    asm volatile("cp.async.cg.shared.global [%0], [%1], 16;"
                 :: "r"(dst), "l"(src) : "memory");
}
__device__ __forceinline__ void cpa16_ca(uint32_t dst, const void* src) {
    asm volatile("cp.async.ca.shared.global [%0], [%1], 16;"
                 :: "r"(dst), "l"(src) : "memory");
}
#define CP_COMMIT() asm volatile("cp.async.commit_group;" ::: "memory")
#define CP_WAIT2()  asm volatile("cp.async.wait_group 2;" ::: "memory")

// ---------------------------------------------------------------------------
__global__ void build_rowidx_kernel() {
    int m = blockIdx.x * 256 + threadIdx.x;
    if (m >= MROWS) return;
    int win = m / NTOK, n = m % NTOK;
    int b  = win >> 6, wi = win & 63;
    int r = (wi >> 3) * WS + n / WS;
    int c = (wi & 7) * WS + n % WS;
    int sh = r + SS; if (sh >= IMG) sh -= IMG;
    int sw = c + SS; if (sw >= IMG) sw -= IMG;
    g_rowidx[m] = (b * IMG + sh) * IMG + sw;
}

__global__ void convert_w_kernel(const float* __restrict__ qkv_w,
                                 const float* __restrict__ proj_w) {
    int i = blockIdx.x * 256 + threadIdx.x;
    if (i < QKVC * CCH) g_wqkv_h[i] = __float2half_rn(qkv_w[i]);
    if (i < CCH * CCH)  g_wp_h[i]   = __float2half_rn(proj_w[i]);
}

// gather x through rowidx and split to fp16 hi/lo (window-row order)
__global__ void convert_x_kernel(const float* __restrict__ x) {
    size_t i = (size_t)blockIdx.x * 256 + threadIdx.x;   // over MROWS*128
    if (i >= (size_t)MROWS * 128) return;
    int m = (int)(i >> 7);
    int c4 = (int)(i & 127) << 2;
    float4 v = *(const float4*)(x + (size_t)g_rowidx[m] * CCH + c4);
    __half h0 = __float2half_rn(v.x);
    __half h1 = __float2half_rn(v.y);
    __half h2 = __float2half_rn(v.z);
    __half h3 = __float2half_rn(v.w);
    uint2 hp, lp;
    hp.x = pack2h(h0, h1); hp.y = pack2h(h2, h3);
    lp.x = pack2h(__float2half_rn(v.x - __half2float(h0)),
                  __float2half_rn(v.y - __half2float(h1)));
    lp.y = pack2h(__float2half_rn(v.z - __half2float(h2)),
                  __float2half_rn(v.w - __half2float(h3)));
    size_t o = (size_t)m * CCH + c4;
    *(uint2*)(g_a_hi + o) = hp;
    *(uint2*)(g_a_lo + o) = lp;
}

// ---------------------------------------------------------------------------
// mma.sync GEMM, cp.async 4-stage pipeline, 2 CTAs/SM.
// BM=BN=128, BK=32, 256 thr (8 warps 4x2, warp tile 32x64).
// Stage (24KB): Ahi @0, Alo @8KB, B @16KB; 128 rows x 64B, chunk-swizzled:
//   phys_chunk = c ^ ((r>>1)&3) ^ ((r>>3)&1)
// Every loop iteration commits exactly one cp.async group (empty at the
// tail) so wait_group 2 always guarantees chunk kt has fully landed.
// ---------------------------------------------------------------------------
#define AHI 0
#define ALO 8192
#define BBB 16384
#define BUFB 24576
#define NSTG 4
#define NKCH 16            // 512/32
#define SMEM_DYN (NSTG * BUFB)

__device__ __forceinline__ uint32_t swz(int r, int c) {
    return (uint32_t)(r * 64 + ((c ^ ((r >> 1) & 3) ^ ((r >> 3) & 1)) << 4));
}

template <bool QKV>
__global__ __launch_bounds__(256, 2)
void gemm_mma_kernel(const float* __restrict__ bias,
                     float* __restrict__ out)
{
    extern __shared__ char smem[];
    const uint32_t sbase = smem_u32(smem);
    const int tid = threadIdx.x;
    const int lane = tid & 31, warp = tid >> 5;
    const int wm = warp >> 1, wn = warp & 1;
    const int bm = blockIdx.y * 128, bn = blockIdx.x * 128;

    const __half* __restrict__ Ah = QKV ? g_a_hi : g_att_hi;
    const __half* __restrict__ Al = QKV ? g_a_lo : g_att_lo;
    const __half* __restrict__ Bw = QKV ? g_wqkv_h : g_wp_h;

    // loader mapping: thread t -> row t/2, k-half t&1 (16 fp16 = 2x16B)
    const int lrow = tid >> 1, half = tid & 1;
    const size_t ga = (size_t)(bm + lrow) * CCH + half * 16;
    const size_t gb = (size_t)(bn + lrow) * CCH + half * 16;
    const uint32_t st0 = swz(lrow, 2 * half);
    const uint32_t st1 = swz(lrow, 2 * half + 1);

    auto issue = [&](int kt, int s) {
        uint32_t b = sbase + s * BUFB;
        const __half* p;
        p = Ah + ga + kt * 32; cpa16_cg(b + AHI + st0, p); cpa16_cg(b + AHI + st1, p + 8);
        p = Al + ga + kt * 32; cpa16_cg(b + ALO + st0, p); cpa16_cg(b + ALO + st1, p + 8);
        p = Bw + gb + kt * 32; cpa16_ca(b + BBB + st0, p); cpa16_ca(b + BBB + st1, p + 8);
        CP_COMMIT();
    };

    // per-lane ldmatrix offsets (stage-relative)
    uint32_t aoff[2][2], boff[2][4];
#pragma unroll
    for (int s = 0; s < 2; s++) {
#pragma unroll
        for (int mt = 0; mt < 2; mt++) {
            int r = wm * 32 + mt * 16 + (lane & 15);
            aoff[s][mt] = swz(r, 2 * s + (lane >> 4));
        }
#pragma unroll
        for (int p = 0; p < 4; p++) {
            int n = wn * 64 + p * 16 + ((lane >> 4) & 1) * 8 + (lane & 7);
            boff[s][p] = swz(n, 2 * s + ((lane >> 3) & 1));
        }
    }

    float acc[2][8][4];
#pragma unroll
    for (int mt = 0; mt < 2; mt++)
#pragma unroll
        for (int nt = 0; nt < 8; nt++)
#pragma unroll
            for (int j = 0; j < 4; j++) acc[mt][nt][j] = 0.f;

    auto compute = [&](uint32_t bb) {
#pragma unroll
        for (int s = 0; s < 2; s++) {
            uint32_t ah[2][4], al_[2][4], bh_[8][2];
#pragma unroll
            for (int mt = 0; mt < 2; mt++) {
                LDSM4(ah[mt][0], ah[mt][1], ah[mt][2], ah[mt][3],
                      bb + AHI + aoff[s][mt]);
                LDSM4(al_[mt][0], al_[mt][1], al_[mt][2], al_[mt][3],
                      bb + ALO + aoff[s][mt]);
            }
#pragma unroll
            for (int p = 0; p < 4; p++) {
                uint32_t t0, t1, t2, t3;
                LDSM4(t0, t1, t2, t3, bb + BBB + boff[s][p]);
                bh_[2 * p][0] = t0; bh_[2 * p][1] = t1;
                bh_[2 * p + 1][0] = t2; bh_[2 * p + 1][1] = t3;
            }
            // all-hi sweep then all-lo sweep: dependent MMAs 15 ops apart
#pragma unroll
            for (int mt = 0; mt < 2; mt++)
#pragma unroll
                for (int nt = 0; nt < 8; nt++)
                    MMA_FP16(acc[mt][nt], ah[mt], bh_[nt]);
#pragma unroll
            for (int mt = 0; mt < 2; mt++)
#pragma unroll
                for (int nt = 0; nt < 8; nt++)
                    MMA_FP16(acc[mt][nt], al_[mt], bh_[nt]);
        }
    };

    // ---- pipeline: 3 chunks in flight, 4 stages ----
    issue(0, 0);
    issue(1, 1);
    issue(2, 2);
    for (int kt = 0; kt < NKCH; kt++) {
        CP_WAIT2();                 // 3 groups pending at top -> kt complete
        __syncthreads();            // visibility + buffer-reuse ordering
        if (kt + 3 < NKCH) issue(kt + 3, (kt + 3) & 3);
        else               CP_COMMIT();     // keep group count uniform
        compute(sbase + (kt & 3) * BUFB);
    }

    // ---- epilogue: fragment -> global fp32 with bias ----
#pragma unroll
    for (int mt = 0; mt < 2; mt++) {
        int mr = bm + wm * 32 + mt * 16 + (lane >> 2);
        size_t r0, r1;
        if (QKV) { r0 = (size_t)mr * QKVC; r1 = (size_t)(mr + 8) * QKVC; }
        else     { r0 = (size_t)g_rowidx[mr] * CCH;
                   r1 = (size_t)g_rowidx[mr + 8] * CCH; }
        float* bp = QKV ? g_qkv : out;
        const int cbase = bn + wn * 64 + 2 * (lane & 3);
        float* p0 = bp + r0 + cbase;
        float* p1 = bp + r1 + cbase;
#pragma unroll
        for (int nt = 0; nt < 8; nt++) {
            float2 bb = *(const float2*)(bias + cbase + nt * 8);
            float2 v0, v1;
            v0.x = acc[mt][nt][0] + bb.x; v0.y = acc[mt][nt][1] + bb.y;
            v1.x = acc[mt][nt][2] + bb.x; v1.y = acc[mt][nt][3] + bb.y;
            *(float2*)(p0 + nt * 8) = v0;
            *(float2*)(p1 + nt * 8) = v1;
        }
    }
}

// ---------------------------------------------------------------------------
// Attention: one block per (window, head). 256 threads.
// Row stride 36 floats (144B = 9x16B): float4 LDS everywhere, conflict-free.
// Output written as fp16 hi/lo (consumed by the proj GEMM 2-term split).
// ---------------------------------------------------------------------------
#define QKS 36

__global__ __launch_bounds__(256)
void attn_kernel(const float* __restrict__ rel)
{
    const int win = blockIdx.x >> 4;
    const int h   = blockIdx.x & 15;
    const int tid = threadIdx.x;

    __shared__ __align__(16) float qs[NTOK * QKS];
    __shared__ __align__(16) float ks[NTOK * QKS];
    __shared__ __align__(16) float vs[NTOK * QKS];
    __shared__ float S[NTOK][50];
    __shared__ float tb[169];
    __shared__ int   lab[NTOK];

    const float scale = 0.17677669529663687f;
    const size_t base = (size_t)win * NTOK * QKVC + h * HD;

    for (int e = tid; e < NTOK * 8; e += 256) {
        int n = e >> 3, c4 = (e & 7) * 4;
        const float* p = g_qkv + base + (size_t)n * QKVC + c4;
        float4 q4 = *(const float4*)(p);
        float4 k4 = *(const float4*)(p + 512);
        float4 v4 = *(const float4*)(p + 1024);
        q4.x *= scale; q4.y *= scale; q4.z *= scale; q4.w *= scale;
        *(float4*)&qs[n * QKS + c4] = q4;
        *(float4*)&ks[n * QKS + c4] = k4;
        *(float4*)&vs[n * QKS + c4] = v4;
    }
    if (tid < 169) tb[tid] = rel[tid * NHEAD + h];
    if (tid < NTOK) {
        int wi = win & 63;
        int r = (wi >> 3) * WS + tid / WS;
        int c = (wi & 7) * WS + tid % WS;
        int rh = (r < IMG - WS) ? 0 : (r < IMG - SS ? 1 : 2);
        int rw = (c < IMG - WS) ? 0 : (c < IMG - SS ? 1 : 2);
        lab[tid] = rh * 3 + rw;
    }
    __syncthreads();

    // scores + bias + mask  (float4 over d: 2 LDS.128 per 4 FMA)
    for (int e = tid; e < NTOK * NTOK; e += 256) {
        int n = (e * 1338) >> 16;          // e/49 for e<2401
        int mm = e - n * NTOK;
        const float* qp = &qs[n * QKS];
        const float* kp = &ks[mm * QKS];
        float a = 0.f;
#pragma unroll
        for (int d4 = 0; d4 < 8; d4++) {
            float4 q = *(const float4*)(qp + d4 * 4);
            float4 k = *(const float4*)(kp + d4 * 4);
            a = fmaf(q.x, k.x, a); a = fmaf(q.y, k.y, a);
            a = fmaf(q.z, k.z, a); a = fmaf(q.w, k.w, a);
        }
        int dr = n / WS - mm / WS + (WS - 1);
        int dc = n % WS - mm % WS + (WS - 1);
        a += tb[dr * (2 * WS - 1) + dc];
        if (lab[n] != lab[mm]) a -= 100.0f;
        S[n][mm] = a;
    }
    __syncthreads();

    // row softmax: warp per row (strided)
    const int warp = tid >> 5, lane = tid & 31;
    for (int n = warp; n < NTOK; n += 8) {
        float v0 = (lane < NTOK)      ? S[n][lane]      : -1e30f;
        float v1 = (lane + 32 < NTOK) ? S[n][lane + 32] : -1e30f;
        float mx = fmaxf(v0, v1);
#pragma unroll
        for (int o = 16; o > 0; o >>= 1)
            mx = fmaxf(mx, __shfl_xor_sync(0xffffffffu, mx, o));
        float e0 = (lane < NTOK)      ? __expf(v0 - mx) : 0.f;
        float e1 = (lane + 32 < NTOK) ? __expf(v1 - mx) : 0.f;
        float sm = e0 + e1;
#pragma unroll
        for (int o = 16; o > 0; o >>= 1)
            sm += __shfl_xor_sync(0xffffffffu, sm, o);
        float inv = 1.0f / sm;
        if (lane < NTOK)      S[n][lane]      = e0 * inv;
        if (lane + 32 < NTOK) S[n][lane + 32] = e1 * inv;
    }
    __syncthreads();

    // out = P @ V -> fp16 hi/lo  (thread = (n, 4 consecutive d))
    const size_t obase = (size_t)win * NTOK * CCH + h * HD;
    for (int e = tid; e < NTOK * 8; e += 256) {
        int n = e >> 3, d4 = (e & 7) * 4;
        float ax = 0.f, ay = 0.f, az = 0.f, aw = 0.f;
#pragma unroll
        for (int mm = 0; mm < NTOK; mm++) {
            float s = S[n][mm];
            float4 v = *(const float4*)&vs[mm * QKS + d4];
            ax = fmaf(s, v.x, ax); ay = fmaf(s, v.y, ay);
            az = fmaf(s, v.z, az); aw = fmaf(s, v.w, aw);
        }
        __half h0 = __float2half_rn(ax);
        __half h1 = __float2half_rn(ay);
        __half h2 = __float2half_rn(az);
        __half h3 = __float2half_rn(aw);
        uint2 hp, lp;
        hp.x = pack2h(h0, h1); hp.y = pack2h(h2, h3);
        lp.x = pack2h(__float2half_rn(ax - __half2float(h0)),
                      __float2half_rn(ay - __half2float(h1)));
        lp.y = pack2h(__float2half_rn(az - __half2float(h2)),
                      __float2half_rn(aw - __half2float(h3)));
        size_t o = obase + (size_t)n * CCH + d4;
        *(uint2*)(g_att_hi + o) = hp;
        *(uint2*)(g_att_lo + o) = lp;
    }
}

// ---------------------------------------------------------------------------
extern "C" void kernel_launch(void* const* d_in, const int* in_sizes, int n_in,
                              void* d_out, int out_size)
{
    const float* x      = (const float*)d_in[0];
    const float* qkv_w  = (const float*)d_in[1];
    const float* qkv_b  = (const float*)d_in[2];
    const float* proj_w = (const float*)d_in[3];
    const float* proj_b = (const float*)d_in[4];
    const float* rel    = (const float*)d_in[5];
    float* out = (float*)d_out;

    cudaFuncSetAttribute(gemm_mma_kernel<true>,
                         cudaFuncAttributeMaxDynamicSharedMemorySize, SMEM_DYN);
    cudaFuncSetAttribute(gemm_mma_kernel<false>,
                         cudaFuncAttributeMaxDynamicSharedMemorySize, SMEM_DYN);

    build_rowidx_kernel<<<(MROWS + 255) / 256, 256>>>();
    convert_w_kernel<<<(QKVC * CCH + 255) / 256, 256>>>(qkv_w, proj_w);
    convert_x_kernel<<<(int)(((size_t)MROWS * 128 + 255) / 256), 256>>>(x);

    // QKV: M=100352, N=1536
    gemm_mma_kernel<true><<<dim3(QKVC / 128, MROWS / 128), 256, SMEM_DYN>>>(
        qkv_b, nullptr);

    attn_kernel<<<TOTWIN * NHEAD, 256>>>(rel);

    // proj: M=100352, N=512 (A = g_att_hi/lo in-kernel, scatter-C to out)
    gemm_mma_kernel<false><<<dim3(CCH / 128, MROWS / 128), 256, SMEM_DYN>>>(
        proj_b, out);
}

// round 13
// speedup vs baseline: 2.3286x; 1.8279x over previous
#include <cuda_runtime.h>
#include <cuda_bf16.h>
#include <cuda_fp16.h>
#include <cstdint>

// ---------------------------------------------------------------------------
// Swin shifted-window attention, B=32 H=W=56 C=512 NH=16 HD=32 WS=7 SS=3
//   k0: build row-index table
//   kw: convert weights fp32 -> fp16
//   kx: convert+gather x     -> g_a_hi/lo (fp16 pair, window-row order)
//   k1: QKV GEMM  mma.sync fp16 2-term split -> g_qkvh (fp16)
//   k2: attention per (window, head), tensor-core FA2-style -> g_att_hi/lo
//   k3: proj GEMM (A split, scatter-C) -> out
//
// R12 -> R13 FIX: attn kernel has 128 threads but the rel-pos table load was
// a single-shot "if (tid < 169)" -- entries 128..168 were uninitialized smem
// (rel_err 0.148). Now a strided loop.
// tcgen05 unavailable (plain sm_103 ptxas target) -> mma.sync + ldmatrix.
// ---------------------------------------------------------------------------

#define BATCH   32
#define IMG     56
#define CCH     512
#define NHEAD   16
#define HD      32
#define WS      7
#define SS      3
#define NTOK    49
#define TOTWIN  2048
#define MROWS   100352
#define QKVC    1536

// scratch (device globals: allocation-free; NEVER passed from host)
__device__ int   g_rowidx[MROWS];
__device__ __half g_qkvh[(size_t)MROWS * QKVC];
__device__ __half g_a_hi[(size_t)MROWS * CCH];
__device__ __half g_a_lo[(size_t)MROWS * CCH];
__device__ __half g_att_hi[(size_t)MROWS * CCH];
__device__ __half g_att_lo[(size_t)MROWS * CCH];
__device__ __half g_wqkv_h[QKVC * CCH];
__device__ __half g_wp_h[CCH * CCH];

__device__ __forceinline__ uint32_t smem_u32(const void* p) {
    uint32_t a;
    asm("{ .reg .u64 t; cvta.to.shared.u64 t, %1; cvt.u32.u64 %0, t; }"
        : "=r"(a) : "l"(p));
    return a;
}
__device__ __forceinline__ uint32_t pack2h(__half a, __half b) {
    return ((uint32_t)__half_as_ushort(b) << 16) | __half_as_ushort(a);
}

#define LDSM4(r0, r1, r2, r3, addr)                                            \
    asm volatile("ldmatrix.sync.aligned.m8n8.x4.shared.b16 {%0,%1,%2,%3}, [%4];" \
                 : "=r"(r0), "=r"(r1), "=r"(r2), "=r"(r3) : "r"(addr))
#define LDSM4T(r0, r1, r2, r3, addr)                                           \
    asm volatile("ldmatrix.sync.aligned.m8n8.x4.trans.shared.b16 {%0,%1,%2,%3}, [%4];" \
                 : "=r"(r0), "=r"(r1), "=r"(r2), "=r"(r3) : "r"(addr))

#define MMA_FP16(d, a, b)                                                      \
    asm volatile("mma.sync.aligned.m16n8k16.row.col.f32.f16.f16.f32 "          \
                 "{%0,%1,%2,%3}, {%4,%5,%6,%7}, {%8,%9}, {%0,%1,%2,%3};"       \
                 : "+f"((d)[0]), "+f"((d)[1]), "+f"((d)[2]), "+f"((d)[3])      \
                 : "r"((a)[0]), "r"((a)[1]), "r"((a)[2]), "r"((a)[3]),         \
                   "r"((b)[0]), "r"((b)[1]))

__device__ __forceinline__ void cpa16_cg(uint32_t dst, const void* src) {
    asm volatile("cp.async.cg.shared.global [%0], [%1], 16;"
                 :: "r"(dst), "l"(src) : "memory");
}
__device__ __forceinline__ void cpa16_ca(uint32_t dst, const void* src) {
    asm volatile("cp.async.ca.shared.global [%0], [%1], 16;"
                 :: "r"(dst), "l"(src) : "memory");
}
#define CP_COMMIT() asm volatile("cp.async.commit_group;" ::: "memory")
#define CP_WAIT2()  asm volatile("cp.async.wait_group 2;" ::: "memory")

// ---------------------------------------------------------------------------
__global__ void build_rowidx_kernel() {
    int m = blockIdx.x * 256 + threadIdx.x;
    if (m >= MROWS) return;
    int win = m / NTOK, n = m % NTOK;
    int b  = win >> 6, wi = win & 63;
    int r = (wi >> 3) * WS + n / WS;
    int c = (wi & 7) * WS + n % WS;
    int sh = r + SS; if (sh >= IMG) sh -= IMG;
    int sw = c + SS; if (sw >= IMG) sw -= IMG;
    g_rowidx[m] = (b * IMG + sh) * IMG + sw;
}

__global__ void convert_w_kernel(const float* __restrict__ qkv_w,
                                 const float* __restrict__ proj_w) {
    int i = blockIdx.x * 256 + threadIdx.x;
    if (i < QKVC * CCH) g_wqkv_h[i] = __float2half_rn(qkv_w[i]);
    if (i < CCH * CCH)  g_wp_h[i]   = __float2half_rn(proj_w[i]);
}

__global__ void convert_x_kernel(const float* __restrict__ x) {
    size_t i = (size_t)blockIdx.x * 256 + threadIdx.x;   // over MROWS*128
    if (i >= (size_t)MROWS * 128) return;
    int m = (int)(i >> 7);
    int c4 = (int)(i & 127) << 2;
    float4 v = *(const float4*)(x + (size_t)g_rowidx[m] * CCH + c4);
    __half h0 = __float2half_rn(v.x);
    __half h1 = __float2half_rn(v.y);
    __half h2 = __float2half_rn(v.z);
    __half h3 = __float2half_rn(v.w);
    uint2 hp, lp;
    hp.x = pack2h(h0, h1); hp.y = pack2h(h2, h3);
    lp.x = pack2h(__float2half_rn(v.x - __half2float(h0)),
                  __float2half_rn(v.y - __half2float(h1)));
    lp.y = pack2h(__float2half_rn(v.z - __half2float(h2)),
                  __float2half_rn(v.w - __half2float(h3)));
    size_t o = (size_t)m * CCH + c4;
    *(uint2*)(g_a_hi + o) = hp;
    *(uint2*)(g_a_lo + o) = lp;
}

// ---------------------------------------------------------------------------
// mma.sync GEMM, cp.async 4-stage pipeline, 2 CTAs/SM.
// BM=BN=128, BK=32, 256 thr (8 warps 4x2, warp tile 32x64).
// QKV=true : C -> g_qkvh (fp16).  QKV=false: C -> out fp32, rowidx scatter.
// ---------------------------------------------------------------------------
#define AHI 0
#define ALO 8192
#define BBB 16384
#define BUFB 24576
#define NSTG 4
#define NKCH 16            // 512/32
#define SMEM_DYN (NSTG * BUFB)

__device__ __forceinline__ uint32_t swz(int r, int c) {
    return (uint32_t)(r * 64 + ((c ^ ((r >> 1) & 3) ^ ((r >> 3) & 1)) << 4));
}

template <bool QKV>
__global__ __launch_bounds__(256, 2)
void gemm_mma_kernel(const float* __restrict__ bias,
                     float* __restrict__ out)
{
    extern __shared__ char smem[];
    const uint32_t sbase = smem_u32(smem);
    const int tid = threadIdx.x;
    const int lane = tid & 31, warp = tid >> 5;
    const int wm = warp >> 1, wn = warp & 1;
    const int bm = blockIdx.y * 128, bn = blockIdx.x * 128;

    const __half* __restrict__ Ah = QKV ? g_a_hi : g_att_hi;
    const __half* __restrict__ Al = QKV ? g_a_lo : g_att_lo;
    const __half* __restrict__ Bw = QKV ? g_wqkv_h : g_wp_h;

    const int lrow = tid >> 1, half = tid & 1;
    const size_t ga = (size_t)(bm + lrow) * CCH + half * 16;
    const size_t gb = (size_t)(bn + lrow) * CCH + half * 16;
    const uint32_t st0 = swz(lrow, 2 * half);
    const uint32_t st1 = swz(lrow, 2 * half + 1);

    auto issue = [&](int kt, int s) {
        uint32_t b = sbase + s * BUFB;
        const __half* p;
        p = Ah + ga + kt * 32; cpa16_cg(b + AHI + st0, p); cpa16_cg(b + AHI + st1, p + 8);
        p = Al + ga + kt * 32; cpa16_cg(b + ALO + st0, p); cpa16_cg(b + ALO + st1, p + 8);
        p = Bw + gb + kt * 32; cpa16_ca(b + BBB + st0, p); cpa16_ca(b + BBB + st1, p + 8);
        CP_COMMIT();
    };

    uint32_t aoff[2][2], boff[2][4];
#pragma unroll
    for (int s = 0; s < 2; s++) {
#pragma unroll
        for (int mt = 0; mt < 2; mt++) {
            int r = wm * 32 + mt * 16 + (lane & 15);
            aoff[s][mt] = swz(r, 2 * s + (lane >> 4));
        }
#pragma unroll
        for (int p = 0; p < 4; p++) {
            int n = wn * 64 + p * 16 + ((lane >> 4) & 1) * 8 + (lane & 7);
            boff[s][p] = swz(n, 2 * s + ((lane >> 3) & 1));
        }
    }

    float acc[2][8][4];
#pragma unroll
    for (int mt = 0; mt < 2; mt++)
#pragma unroll
        for (int nt = 0; nt < 8; nt++)
#pragma unroll
            for (int j = 0; j < 4; j++) acc[mt][nt][j] = 0.f;

    auto compute = [&](uint32_t bb) {
#pragma unroll
        for (int s = 0; s < 2; s++) {
            uint32_t ah[2][4], al_[2][4], bh_[8][2];
#pragma unroll
            for (int mt = 0; mt < 2; mt++) {
                LDSM4(ah[mt][0], ah[mt][1], ah[mt][2], ah[mt][3],
                      bb + AHI + aoff[s][mt]);
                LDSM4(al_[mt][0], al_[mt][1], al_[mt][2], al_[mt][3],
                      bb + ALO + aoff[s][mt]);
            }
#pragma unroll
            for (int p = 0; p < 4; p++) {
                uint32_t t0, t1, t2, t3;
                LDSM4(t0, t1, t2, t3, bb + BBB + boff[s][p]);
                bh_[2 * p][0] = t0; bh_[2 * p][1] = t1;
                bh_[2 * p + 1][0] = t2; bh_[2 * p + 1][1] = t3;
            }
#pragma unroll
            for (int mt = 0; mt < 2; mt++)
#pragma unroll
                for (int nt = 0; nt < 8; nt++)
                    MMA_FP16(acc[mt][nt], ah[mt], bh_[nt]);
#pragma unroll
            for (int mt = 0; mt < 2; mt++)
#pragma unroll
                for (int nt = 0; nt < 8; nt++)
                    MMA_FP16(acc[mt][nt], al_[mt], bh_[nt]);
        }
    };

    issue(0, 0);
    issue(1, 1);
    issue(2, 2);
    for (int kt = 0; kt < NKCH; kt++) {
        CP_WAIT2();
        __syncthreads();
        if (kt + 3 < NKCH) issue(kt + 3, (kt + 3) & 3);
        else               CP_COMMIT();     // keep group count uniform
        compute(sbase + (kt & 3) * BUFB);
    }

    // ---- epilogue ----
#pragma unroll
    for (int mt = 0; mt < 2; mt++) {
        int mr = bm + wm * 32 + mt * 16 + (lane >> 2);
        const int cbase = bn + wn * 64 + 2 * (lane & 3);
        if (QKV) {
            size_t r0 = (size_t)mr * QKVC, r1 = (size_t)(mr + 8) * QKVC;
#pragma unroll
            for (int nt = 0; nt < 8; nt++) {
                float2 bb = *(const float2*)(bias + cbase + nt * 8);
                uint32_t u0 = pack2h(__float2half_rn(acc[mt][nt][0] + bb.x),
                                     __float2half_rn(acc[mt][nt][1] + bb.y));
                uint32_t u1 = pack2h(__float2half_rn(acc[mt][nt][2] + bb.x),
                                     __float2half_rn(acc[mt][nt][3] + bb.y));
                *(uint32_t*)(g_qkvh + r0 + cbase + nt * 8) = u0;
                *(uint32_t*)(g_qkvh + r1 + cbase + nt * 8) = u1;
            }
        } else {
            size_t r0 = (size_t)g_rowidx[mr] * CCH;
            size_t r1 = (size_t)g_rowidx[mr + 8] * CCH;
            float* p0 = out + r0 + cbase;
            float* p1 = out + r1 + cbase;
#pragma unroll
            for (int nt = 0; nt < 8; nt++) {
                float2 bb = *(const float2*)(bias + cbase + nt * 8);
                float2 v0, v1;
                v0.x = acc[mt][nt][0] + bb.x; v0.y = acc[mt][nt][1] + bb.y;
                v1.x = acc[mt][nt][2] + bb.x; v1.y = acc[mt][nt][3] + bb.y;
                *(float2*)(p0 + nt * 8) = v0;
                *(float2*)(p1 + nt * 8) = v1;
            }
        }
    }
}

// ---------------------------------------------------------------------------
// Attention: block = (window, head), 128 thr = 4 warps, warp = one m16 tile.
// q/k/v fp16 in smem (row stride 40 halves = 80B, 16B-aligned, conflict-free
// ldmatrix). S via mma fragments, in-register softmax (quad shfl_xor), P
// repacked to A-frags in registers, PV via trans ldmatrix. Bias matrix
// (rel-pos + shift mask, cols 49-55 = -1e30, pad rows 0) built per block.
// ---------------------------------------------------------------------------
#define ASTR 40

__global__ __launch_bounds__(128)
void attn_kernel(const float* __restrict__ rel)
{
    const int win = blockIdx.x >> 4;
    const int h   = blockIdx.x & 15;
    const int tid = threadIdx.x;
    const int lane = tid & 31, warp = tid >> 5;

    __shared__ __align__(16) __half qs[64 * ASTR];
    __shared__ __align__(16) __half ks[64 * ASTR];
    __shared__ __align__(16) __half vs[64 * ASTR];
    __shared__ float bm_s[64 * 56];
    __shared__ float tb[169];
    __shared__ int   lab[NTOK];

    // ---- loads: q/k/v tiles + rel table + labels ----
    for (int i = tid; i < 169; i += 128)          // FIX: strided (128 thr!)
        tb[i] = rel[i * NHEAD + h];
    if (tid < NTOK) {
        int wi = win & 63;
        int r = (wi >> 3) * WS + tid / WS;
        int c = (wi & 7) * WS + tid % WS;
        int rh = (r < IMG - WS) ? 0 : (r < IMG - SS ? 1 : 2);
        int rw = (c < IMG - WS) ? 0 : (c < IMG - SS ? 1 : 2);
        lab[tid] = rh * 3 + rw;
    }
    const size_t base = (size_t)(win * NTOK) * QKVC + h * HD;
    for (int e = tid; e < NTOK * 8; e += 128) {
        int n = e >> 3, c4 = (e & 7) * 4;
        const __half* p = g_qkvh + base + (size_t)n * QKVC + c4;
        *(uint2*)&qs[n * ASTR + c4] = *(const uint2*)(p);
        *(uint2*)&ks[n * ASTR + c4] = *(const uint2*)(p + 512);
        *(uint2*)&vs[n * ASTR + c4] = *(const uint2*)(p + 1024);
    }
    for (int e = tid; e < 15 * 8; e += 128) {     // zero pad rows 49..63
        int n = NTOK + (e >> 3), c4 = (e & 7) * 4;
        *(uint2*)&qs[n * ASTR + c4] = make_uint2(0, 0);
        *(uint2*)&ks[n * ASTR + c4] = make_uint2(0, 0);
        *(uint2*)&vs[n * ASTR + c4] = make_uint2(0, 0);
    }
    __syncthreads();

    // ---- bias matrix: rel-pos + shift mask; col>=49 masked; row>=49 zero ----
    for (int idx = tid; idx < 64 * 56; idx += 128) {
        int r = idx / 56, c = idx % 56;
        float v;
        if (r >= NTOK)      v = 0.0f;
        else if (c >= NTOK) v = -1e30f;
        else {
            int rr = r / WS, rm = r % WS, cr = c / WS, cm = c % WS;
            v = tb[(rr - cr + 6) * 13 + (rm - cm + 6)];
            if (lab[r] != lab[c]) v -= 100.0f;
        }
        bm_s[idx] = v;
    }
    __syncthreads();

    // ---- per-warp fragment compute ----
    const int m0 = warp * 16;
    const int g = lane >> 2, t = lane & 3;
    const int lane15 = lane & 15, lhalf = lane >> 4;

    const uint32_t qb = smem_u32(qs), kb = smem_u32(ks), vb = smem_u32(vs);

    // A frags for both k16 steps (d = 0, 16)
    uint32_t af[2][4];
    {
        uint32_t aa = qb + ((m0 + lane15) * ASTR + lhalf * 8) * 2;
        LDSM4(af[0][0], af[0][1], af[0][2], af[0][3], aa);
        LDSM4(af[1][0], af[1][1], af[1][2], af[1][3], aa + 32);
    }

    float sacc[7][4];
#pragma unroll
    for (int j = 0; j < 7; j++)
#pragma unroll
        for (int i = 0; i < 4; i++) sacc[j][i] = 0.f;

#pragma unroll
    for (int nc = 0; nc < 4; nc++) {
        uint32_t ka = kb + ((nc * 16 + lane15) * ASTR + lhalf * 8) * 2;
#pragma unroll
        for (int kk = 0; kk < 2; kk++) {
            uint32_t r0, r1, r2, r3;
            LDSM4(r0, r1, r2, r3, ka + kk * 32);
            uint32_t blo[2] = { r0, r2 };      // tokens nc*16+0..7
            uint32_t bhi[2] = { r1, r3 };      // tokens nc*16+8..15
            MMA_FP16(sacc[2 * nc], af[kk], blo);
            if (2 * nc + 1 < 7) MMA_FP16(sacc[2 * nc + 1], af[kk], bhi);
        }
    }

    // ---- scale + bias, softmax over rows (m0+g) and (m0+g+8) ----
    const float scale = 0.17677669529663687f;   // 32^-0.5
    const int r_lo = m0 + g, r_hi = m0 + g + 8;
#pragma unroll
    for (int j = 0; j < 7; j++) {
        int c0 = j * 8 + 2 * t;
        sacc[j][0] = sacc[j][0] * scale + bm_s[r_lo * 56 + c0];
        sacc[j][1] = sacc[j][1] * scale + bm_s[r_lo * 56 + c0 + 1];
        sacc[j][2] = sacc[j][2] * scale + bm_s[r_hi * 56 + c0];
        sacc[j][3] = sacc[j][3] * scale + bm_s[r_hi * 56 + c0 + 1];
    }
    float mlo = -1e30f, mhi = -1e30f;
#pragma unroll
    for (int j = 0; j < 7; j++) {
        mlo = fmaxf(mlo, fmaxf(sacc[j][0], sacc[j][1]));
        mhi = fmaxf(mhi, fmaxf(sacc[j][2], sacc[j][3]));
    }
    mlo = fmaxf(mlo, __shfl_xor_sync(0xffffffffu, mlo, 1));
    mlo = fmaxf(mlo, __shfl_xor_sync(0xffffffffu, mlo, 2));
    mhi = fmaxf(mhi, __shfl_xor_sync(0xffffffffu, mhi, 1));
    mhi = fmaxf(mhi, __shfl_xor_sync(0xffffffffu, mhi, 2));
    float slo = 0.f, shi = 0.f;
#pragma unroll
    for (int j = 0; j < 7; j++) {
        sacc[j][0] = __expf(sacc[j][0] - mlo);
        sacc[j][1] = __expf(sacc[j][1] - mlo);
        sacc[j][2] = __expf(sacc[j][2] - mhi);
        sacc[j][3] = __expf(sacc[j][3] - mhi);
        slo += sacc[j][0] + sacc[j][1];
        shi += sacc[j][2] + sacc[j][3];
    }
    slo += __shfl_xor_sync(0xffffffffu, slo, 1);
    slo += __shfl_xor_sync(0xffffffffu, slo, 2);
    shi += __shfl_xor_sync(0xffffffffu, shi, 1);
    shi += __shfl_xor_sync(0xffffffffu, shi, 2);
    const float ilo = 1.0f / slo, ihi = 1.0f / shi;

    // ---- P fragments (normalized, fp16) ----
    uint32_t pf[7][2];
#pragma unroll
    for (int j = 0; j < 7; j++) {
        pf[j][0] = pack2h(__float2half_rn(sacc[j][0] * ilo),
                          __float2half_rn(sacc[j][1] * ilo));
        pf[j][1] = pack2h(__float2half_rn(sacc[j][2] * ihi),
                          __float2half_rn(sacc[j][3] * ihi));
    }

    // ---- PV: out[m16 x 32] = P[m16 x 64pad] @ V[64pad x 32] ----
    float oacc[4][4];
#pragma unroll
    for (int nt = 0; nt < 4; nt++)
#pragma unroll
        for (int i = 0; i < 4; i++) oacc[nt][i] = 0.f;

    const int grp = lane >> 3, lr8 = lane & 7;
    const int vrow_off = lr8 + ((grp & 1) ? 8 : 0);
    const int vcol_off = (grp >= 2) ? 8 : 0;
#pragma unroll
    for (int kk = 0; kk < 4; kk++) {
        uint32_t a[4];
        a[0] = pf[2 * kk][0];
        a[1] = pf[2 * kk][1];
        a[2] = (2 * kk + 1 < 7) ? pf[2 * kk + 1][0] : 0u;
        a[3] = (2 * kk + 1 < 7) ? pf[2 * kk + 1][1] : 0u;
#pragma unroll
        for (int nv = 0; nv < 2; nv++) {
            uint32_t va = vb + ((kk * 16 + vrow_off) * ASTR + nv * 16 + vcol_off) * 2;
            uint32_t r0, r1, r2, r3;
            LDSM4T(r0, r1, r2, r3, va);
            uint32_t b0[2] = { r0, r1 };
            uint32_t b1[2] = { r2, r3 };
            MMA_FP16(oacc[2 * nv], a, b0);
            MMA_FP16(oacc[2 * nv + 1], a, b1);
        }
    }

    // ---- epilogue: rows m0+g, m0+g+8 -> g_att_hi/lo ----
    const size_t obase = (size_t)(win * NTOK) * CCH + h * HD;
    if (r_lo < NTOK) {
        size_t rb = obase + (size_t)r_lo * CCH;
#pragma unroll
        for (int nt = 0; nt < 4; nt++) {
            int col = nt * 8 + 2 * t;
            float x0 = oacc[nt][0], x1 = oacc[nt][1];
            __half h0 = __float2half_rn(x0), h1 = __float2half_rn(x1);
            *(uint32_t*)(g_att_hi + rb + col) = pack2h(h0, h1);
            *(uint32_t*)(g_att_lo + rb + col) =
                pack2h(__float2half_rn(x0 - __half2float(h0)),
                       __float2half_rn(x1 - __half2float(h1)));
        }
    }
    if (r_hi < NTOK) {
        size_t rb = obase + (size_t)r_hi * CCH;
#pragma unroll
        for (int nt = 0; nt < 4; nt++) {
            int col = nt * 8 + 2 * t;
            float x0 = oacc[nt][2], x1 = oacc[nt][3];
            __half h0 = __float2half_rn(x0), h1 = __float2half_rn(x1);
            *(uint32_t*)(g_att_hi + rb + col) = pack2h(h0, h1);
            *(uint32_t*)(g_att_lo + rb + col) =
                pack2h(__float2half_rn(x0 - __half2float(h0)),
                       __float2half_rn(x1 - __half2float(h1)));
        }
    }
}

// ---------------------------------------------------------------------------
extern "C" void kernel_launch(void* const* d_in, const int* in_sizes, int n_in,
                              void* d_out, int out_size)
{
    const float* x      = (const float*)d_in[0];
    const float* qkv_w  = (const float*)d_in[1];
    const float* qkv_b  = (const float*)d_in[2];
    const float* proj_w = (const float*)d_in[3];
    const float* proj_b = (const float*)d_in[4];
    const float* rel    = (const float*)d_in[5];
    float* out = (float*)d_out;

    cudaFuncSetAttribute(gemm_mma_kernel<true>,
                         cudaFuncAttributeMaxDynamicSharedMemorySize, SMEM_DYN);
    cudaFuncSetAttribute(gemm_mma_kernel<false>,
                         cudaFuncAttributeMaxDynamicSharedMemorySize, SMEM_DYN);

    build_rowidx_kernel<<<(MROWS + 255) / 256, 256>>>();
    convert_w_kernel<<<(QKVC * CCH + 255) / 256, 256>>>(qkv_w, proj_w);
    convert_x_kernel<<<(int)(((size_t)MROWS * 128 + 255) / 256), 256>>>(x);

    // QKV: M=100352, N=1536 -> fp16 g_qkvh
    gemm_mma_kernel<true><<<dim3(QKVC / 128, MROWS / 128), 256, SMEM_DYN>>>(
        qkv_b, nullptr);

    attn_kernel<<<TOTWIN * NHEAD, 128>>>(rel);

    // proj: M=100352, N=512 (A = g_att_hi/lo, scatter-C to out)
    gemm_mma_kernel<false><<<dim3(CCH / 128, MROWS / 128), 256, SMEM_DYN>>>(
        proj_b, out);
}

// round 14
// speedup vs baseline: 3.3434x; 1.4358x over previous
#include <cuda_runtime.h>
#include <cuda_bf16.h>
#include <cuda_fp16.h>
#include <cstdint>

// ---------------------------------------------------------------------------
// Swin shifted-window attention, B=32 H=W=56 C=512 NH=16 HD=32 WS=7 SS=3
//   k0: build row-index table
//   kw: convert weights fp32 -> fp16
//   kx: convert+gather x     -> g_a_h (fp16, window-row order)
//   k1: QKV GEMM  mma.sync fp16 (single), cp.async 6-stage -> g_qkvh (fp16)
//   k2: attention per (window, head), tensor-core FA2-style -> g_att_h (fp16)
//   k3: proj GEMM (scatter-C) -> out (fp32)
//
// R13 -> R14: dropped the A-side hi/lo split everywhere. Error budget
// (norm-based rel_err): R13 measured 3.59e-4 with A exact; two extra
// independent ~2.8e-4 fp16-A terms add in quadrature -> ~5.4e-4 < 1e-3.
// Halves GEMM MMA work (the pipe is MMA-work-bound: R10 vs R11 evidence),
// shrinks stage to 16KB -> 6-stage cp.async pipeline, 5 loads in flight.
// tcgen05 unavailable (plain sm_103 ptxas target) -> mma.sync + ldmatrix.
// ---------------------------------------------------------------------------

#define BATCH   32
#define IMG     56
#define CCH     512
#define NHEAD   16
#define HD      32
#define WS      7
#define SS      3
#define NTOK    49
#define TOTWIN  2048
#define MROWS   100352
#define QKVC    1536

// scratch (device globals: allocation-free; NEVER passed from host)
__device__ int   g_rowidx[MROWS];
__device__ __half g_qkvh[(size_t)MROWS * QKVC];
__device__ __half g_a_h[(size_t)MROWS * CCH];
__device__ __half g_att_h[(size_t)MROWS * CCH];
__device__ __half g_wqkv_h[QKVC * CCH];
__device__ __half g_wp_h[CCH * CCH];

__device__ __forceinline__ uint32_t smem_u32(const void* p) {
    uint32_t a;
    asm("{ .reg .u64 t; cvta.to.shared.u64 t, %1; cvt.u32.u64 %0, t; }"
        : "=r"(a) : "l"(p));
    return a;
}
__device__ __forceinline__ uint32_t pack2h(__half a, __half b) {
    return ((uint32_t)__half_as_ushort(b) << 16) | __half_as_ushort(a);
}

#define LDSM4(r0, r1, r2, r3, addr)                                            \
    asm volatile("ldmatrix.sync.aligned.m8n8.x4.shared.b16 {%0,%1,%2,%3}, [%4];" \
                 : "=r"(r0), "=r"(r1), "=r"(r2), "=r"(r3) : "r"(addr))
#define LDSM4T(r0, r1, r2, r3, addr)                                           \
    asm volatile("ldmatrix.sync.aligned.m8n8.x4.trans.shared.b16 {%0,%1,%2,%3}, [%4];" \
                 : "=r"(r0), "=r"(r1), "=r"(r2), "=r"(r3) : "r"(addr))

#define MMA_FP16(d, a, b)                                                      \
    asm volatile("mma.sync.aligned.m16n8k16.row.col.f32.f16.f16.f32 "          \
                 "{%0,%1,%2,%3}, {%4,%5,%6,%7}, {%8,%9}, {%0,%1,%2,%3};"       \
                 : "+f"((d)[0]), "+f"((d)[1]), "+f"((d)[2]), "+f"((d)[3])      \
                 : "r"((a)[0]), "r"((a)[1]), "r"((a)[2]), "r"((a)[3]),         \
                   "r"((b)[0]), "r"((b)[1]))

__device__ __forceinline__ void cpa16_cg(uint32_t dst, const void* src) {
    asm volatile("cp.async.cg.shared.global [%0], [%1], 16;"
                 :: "r"(dst), "l"(src) : "memory");
}
__device__ __forceinline__ void cpa16_ca(uint32_t dst, const void* src) {
    asm volatile("cp.async.ca.shared.global [%0], [%1], 16;"
                 :: "r"(dst), "l"(src) : "memory");
}
#define CP_COMMIT() asm volatile("cp.async.commit_group;" ::: "memory")
#define CP_WAIT4()  asm volatile("cp.async.wait_group 4;" ::: "memory")

// ---------------------------------------------------------------------------
__global__ void build_rowidx_kernel() {
    int m = blockIdx.x * 256 + threadIdx.x;
    if (m >= MROWS) return;
    int win = m / NTOK, n = m % NTOK;
    int b  = win >> 6, wi = win & 63;
    int r = (wi >> 3) * WS + n / WS;
    int c = (wi & 7) * WS + n % WS;
    int sh = r + SS; if (sh >= IMG) sh -= IMG;
    int sw = c + SS; if (sw >= IMG) sw -= IMG;
    g_rowidx[m] = (b * IMG + sh) * IMG + sw;
}

__global__ void convert_w_kernel(const float* __restrict__ qkv_w,
                                 const float* __restrict__ proj_w) {
    int i = blockIdx.x * 256 + threadIdx.x;
    if (i < QKVC * CCH) g_wqkv_h[i] = __float2half_rn(qkv_w[i]);
    if (i < CCH * CCH)  g_wp_h[i]   = __float2half_rn(proj_w[i]);
}

// gather x through rowidx, fp16 (window-row order)
__global__ void convert_x_kernel(const float* __restrict__ x) {
    size_t i = (size_t)blockIdx.x * 256 + threadIdx.x;   // over MROWS*128
    if (i >= (size_t)MROWS * 128) return;
    int m = (int)(i >> 7);
    int c4 = (int)(i & 127) << 2;
    float4 v = *(const float4*)(x + (size_t)g_rowidx[m] * CCH + c4);
    uint2 hp;
    hp.x = pack2h(__float2half_rn(v.x), __float2half_rn(v.y));
    hp.y = pack2h(__float2half_rn(v.z), __float2half_rn(v.w));
    *(uint2*)(g_a_h + (size_t)m * CCH + c4) = hp;
}

// ---------------------------------------------------------------------------
// mma.sync fp16 GEMM, cp.async 6-stage pipeline (5 loads in flight), 2 CTA/SM.
// BM=BN=128, BK=32, 256 thr (8 warps 4x2, warp tile 32x64).
// Stage (16KB): A @0, B @8KB; 128 rows x 64B, chunk-swizzled:
//   phys_chunk = c ^ ((r>>1)&3) ^ ((r>>3)&1)
// QKV=true : C -> g_qkvh (fp16).  QKV=false: C -> out fp32, rowidx scatter.
// ---------------------------------------------------------------------------
#define AOFF 0
#define BOFF 8192
#define BUFB 16384
#define NSTG 6
#define NKCH 16            // 512/32
#define SMEM_DYN (NSTG * BUFB)

__device__ __forceinline__ uint32_t swz(int r, int c) {
    return (uint32_t)(r * 64 + ((c ^ ((r >> 1) & 3) ^ ((r >> 3) & 1)) << 4));
}

template <bool QKV>
__global__ __launch_bounds__(256, 2)
void gemm_mma_kernel(const float* __restrict__ bias,
                     float* __restrict__ out)
{
    extern __shared__ char smem[];
    const uint32_t sbase = smem_u32(smem);
    const int tid = threadIdx.x;
    const int lane = tid & 31, warp = tid >> 5;
    const int wm = warp >> 1, wn = warp & 1;
    const int bm = blockIdx.y * 128, bn = blockIdx.x * 128;

    const __half* __restrict__ Aw = QKV ? g_a_h : g_att_h;
    const __half* __restrict__ Bw = QKV ? g_wqkv_h : g_wp_h;

    const int lrow = tid >> 1, half = tid & 1;
    const size_t ga = (size_t)(bm + lrow) * CCH + half * 16;
    const size_t gb = (size_t)(bn + lrow) * CCH + half * 16;
    const uint32_t st0 = swz(lrow, 2 * half);
    const uint32_t st1 = swz(lrow, 2 * half + 1);

    auto issue = [&](int kt, int s) {
        uint32_t b = sbase + s * BUFB;
        const __half* p;
        p = Aw + ga + kt * 32; cpa16_cg(b + AOFF + st0, p); cpa16_cg(b + AOFF + st1, p + 8);
        p = Bw + gb + kt * 32; cpa16_ca(b + BOFF + st0, p); cpa16_ca(b + BOFF + st1, p + 8);
        CP_COMMIT();
    };

    uint32_t aoff_[2][2], boff[2][4];
#pragma unroll
    for (int s = 0; s < 2; s++) {
#pragma unroll
        for (int mt = 0; mt < 2; mt++) {
            int r = wm * 32 + mt * 16 + (lane & 15);
            aoff_[s][mt] = swz(r, 2 * s + (lane >> 4));
        }
#pragma unroll
        for (int p = 0; p < 4; p++) {
            int n = wn * 64 + p * 16 + ((lane >> 4) & 1) * 8 + (lane & 7);
            boff[s][p] = swz(n, 2 * s + ((lane >> 3) & 1));
        }
    }

    float acc[2][8][4];
#pragma unroll
    for (int mt = 0; mt < 2; mt++)
#pragma unroll
        for (int nt = 0; nt < 8; nt++)
#pragma unroll
            for (int j = 0; j < 4; j++) acc[mt][nt][j] = 0.f;

    auto compute = [&](uint32_t bb) {
#pragma unroll
        for (int s = 0; s < 2; s++) {
            uint32_t ah[2][4], bh_[8][2];
#pragma unroll
            for (int mt = 0; mt < 2; mt++)
                LDSM4(ah[mt][0], ah[mt][1], ah[mt][2], ah[mt][3],
                      bb + AOFF + aoff_[s][mt]);
#pragma unroll
            for (int p = 0; p < 4; p++) {
                uint32_t t0, t1, t2, t3;
                LDSM4(t0, t1, t2, t3, bb + BOFF + boff[s][p]);
                bh_[2 * p][0] = t0; bh_[2 * p][1] = t1;
                bh_[2 * p + 1][0] = t2; bh_[2 * p + 1][1] = t3;
            }
#pragma unroll
            for (int mt = 0; mt < 2; mt++)
#pragma unroll
                for (int nt = 0; nt < 8; nt++)
                    MMA_FP16(acc[mt][nt], ah[mt], bh_[nt]);
        }
    };

    // ---- pipeline: 5 chunks in flight, 6 stages ----
    issue(0, 0); issue(1, 1); issue(2, 2); issue(3, 3); issue(4, 4);
    for (int kt = 0; kt < NKCH; kt++) {
        CP_WAIT4();                 // 5 groups pending at top -> kt complete
        __syncthreads();            // all warps done with stage being reused
        if (kt + 5 < NKCH) issue(kt + 5, (kt + 5) % NSTG);
        else               CP_COMMIT();     // keep group count uniform
        compute(sbase + (kt % NSTG) * BUFB);
    }

    // ---- epilogue ----
#pragma unroll
    for (int mt = 0; mt < 2; mt++) {
        int mr = bm + wm * 32 + mt * 16 + (lane >> 2);
        const int cbase = bn + wn * 64 + 2 * (lane & 3);
        if (QKV) {
            size_t r0 = (size_t)mr * QKVC, r1 = (size_t)(mr + 8) * QKVC;
#pragma unroll
            for (int nt = 0; nt < 8; nt++) {
                float2 bb = *(const float2*)(bias + cbase + nt * 8);
                uint32_t u0 = pack2h(__float2half_rn(acc[mt][nt][0] + bb.x),
                                     __float2half_rn(acc[mt][nt][1] + bb.y));
                uint32_t u1 = pack2h(__float2half_rn(acc[mt][nt][2] + bb.x),
                                     __float2half_rn(acc[mt][nt][3] + bb.y));
                *(uint32_t*)(g_qkvh + r0 + cbase + nt * 8) = u0;
                *(uint32_t*)(g_qkvh + r1 + cbase + nt * 8) = u1;
            }
        } else {
            size_t r0 = (size_t)g_rowidx[mr] * CCH;
            size_t r1 = (size_t)g_rowidx[mr + 8] * CCH;
            float* p0 = out + r0 + cbase;
            float* p1 = out + r1 + cbase;
#pragma unroll
            for (int nt = 0; nt < 8; nt++) {
                float2 bb = *(const float2*)(bias + cbase + nt * 8);
                float2 v0, v1;
                v0.x = acc[mt][nt][0] + bb.x; v0.y = acc[mt][nt][1] + bb.y;
                v1.x = acc[mt][nt][2] + bb.x; v1.y = acc[mt][nt][3] + bb.y;
                *(float2*)(p0 + nt * 8) = v0;
                *(float2*)(p1 + nt * 8) = v1;
            }
        }
    }
}

// ---------------------------------------------------------------------------
// Attention: block = (window, head), 128 thr = 4 warps, warp = one m16 tile.
// q/k/v fp16 in smem (row stride 40 halves = 80B, conflict-free ldmatrix).
// S via mma fragments, in-register softmax (quad shfl_xor), P repacked to
// A-frags in registers, PV via trans ldmatrix. Bias matrix (rel-pos + shift
// mask, cols 49-55 = -1e30, pad rows 0) built per block.
// ---------------------------------------------------------------------------
#define ASTR 40

__global__ __launch_bounds__(128)
void attn_kernel(const float* __restrict__ rel)
{
    const int win = blockIdx.x >> 4;
    const int h   = blockIdx.x & 15;
    const int tid = threadIdx.x;
    const int lane = tid & 31, warp = tid >> 5;

    __shared__ __align__(16) __half qs[64 * ASTR];
    __shared__ __align__(16) __half ks[64 * ASTR];
    __shared__ __align__(16) __half vs[64 * ASTR];
    __shared__ float bm_s[64 * 56];
    __shared__ float tb[169];
    __shared__ int   lab[NTOK];

    for (int i = tid; i < 169; i += 128)          // strided (128 threads!)
        tb[i] = rel[i * NHEAD + h];
    if (tid < NTOK) {
        int wi = win & 63;
        int r = (wi >> 3) * WS + tid / WS;
        int c = (wi & 7) * WS + tid % WS;
        int rh = (r < IMG - WS) ? 0 : (r < IMG - SS ? 1 : 2);
        int rw = (c < IMG - WS) ? 0 : (c < IMG - SS ? 1 : 2);
        lab[tid] = rh * 3 + rw;
    }
    const size_t base = (size_t)(win * NTOK) * QKVC + h * HD;
    for (int e = tid; e < NTOK * 8; e += 128) {
        int n = e >> 3, c4 = (e & 7) * 4;
        const __half* p = g_qkvh + base + (size_t)n * QKVC + c4;
        *(uint2*)&qs[n * ASTR + c4] = *(const uint2*)(p);
        *(uint2*)&ks[n * ASTR + c4] = *(const uint2*)(p + 512);
        *(uint2*)&vs[n * ASTR + c4] = *(const uint2*)(p + 1024);
    }
    for (int e = tid; e < 15 * 8; e += 128) {     // zero pad rows 49..63
        int n = NTOK + (e >> 3), c4 = (e & 7) * 4;
        *(uint2*)&qs[n * ASTR + c4] = make_uint2(0, 0);
        *(uint2*)&ks[n * ASTR + c4] = make_uint2(0, 0);
        *(uint2*)&vs[n * ASTR + c4] = make_uint2(0, 0);
    }
    __syncthreads();

    for (int idx = tid; idx < 64 * 56; idx += 128) {
        int r = idx / 56, c = idx % 56;
        float v;
        if (r >= NTOK)      v = 0.0f;
        else if (c >= NTOK) v = -1e30f;
        else {
            int rr = r / WS, rm = r % WS, cr = c / WS, cm = c % WS;
            v = tb[(rr - cr + 6) * 13 + (rm - cm + 6)];
            if (lab[r] != lab[c]) v -= 100.0f;
        }
        bm_s[idx] = v;
    }
    __syncthreads();

    const int m0 = warp * 16;
    const int g = lane >> 2, t = lane & 3;
    const int lane15 = lane & 15, lhalf = lane >> 4;
    const uint32_t qb = smem_u32(qs), kb = smem_u32(ks), vb = smem_u32(vs);

    uint32_t af[2][4];
    {
        uint32_t aa = qb + ((m0 + lane15) * ASTR + lhalf * 8) * 2;
        LDSM4(af[0][0], af[0][1], af[0][2], af[0][3], aa);
        LDSM4(af[1][0], af[1][1], af[1][2], af[1][3], aa + 32);
    }

    float sacc[7][4];
#pragma unroll
    for (int j = 0; j < 7; j++)
#pragma unroll
        for (int i = 0; i < 4; i++) sacc[j][i] = 0.f;

#pragma unroll
    for (int nc = 0; nc < 4; nc++) {
        uint32_t ka = kb + ((nc * 16 + lane15) * ASTR + lhalf * 8) * 2;
#pragma unroll
        for (int kk = 0; kk < 2; kk++) {
            uint32_t r0, r1, r2, r3;
            LDSM4(r0, r1, r2, r3, ka + kk * 32);
            uint32_t blo[2] = { r0, r2 };
            uint32_t bhi[2] = { r1, r3 };
            MMA_FP16(sacc[2 * nc], af[kk], blo);
            if (2 * nc + 1 < 7) MMA_FP16(sacc[2 * nc + 1], af[kk], bhi);
        }
    }

    const float scale = 0.17677669529663687f;   // 32^-0.5
    const int r_lo = m0 + g, r_hi = m0 + g + 8;
#pragma unroll
    for (int j = 0; j < 7; j++) {
        int c0 = j * 8 + 2 * t;
        sacc[j][0] = sacc[j][0] * scale + bm_s[r_lo * 56 + c0];
        sacc[j][1] = sacc[j][1] * scale + bm_s[r_lo * 56 + c0 + 1];
        sacc[j][2] = sacc[j][2] * scale + bm_s[r_hi * 56 + c0];
        sacc[j][3] = sacc[j][3] * scale + bm_s[r_hi * 56 + c0 + 1];
    }
    float mlo = -1e30f, mhi = -1e30f;
#pragma unroll
    for (int j = 0; j < 7; j++) {
        mlo = fmaxf(mlo, fmaxf(sacc[j][0], sacc[j][1]));
        mhi = fmaxf(mhi, fmaxf(sacc[j][2], sacc[j][3]));
    }
    mlo = fmaxf(mlo, __shfl_xor_sync(0xffffffffu, mlo, 1));
    mlo = fmaxf(mlo, __shfl_xor_sync(0xffffffffu, mlo, 2));
    mhi = fmaxf(mhi, __shfl_xor_sync(0xffffffffu, mhi, 1));
    mhi = fmaxf(mhi, __shfl_xor_sync(0xffffffffu, mhi, 2));
    float slo = 0.f, shi = 0.f;
#pragma unroll
    for (int j = 0; j < 7; j++) {
        sacc[j][0] = __expf(sacc[j][0] - mlo);
        sacc[j][1] = __expf(sacc[j][1] - mlo);
        sacc[j][2] = __expf(sacc[j][2] - mhi);
        sacc[j][3] = __expf(sacc[j][3] - mhi);
        slo += sacc[j][0] + sacc[j][1];
        shi += sacc[j][2] + sacc[j][3];
    }
    slo += __shfl_xor_sync(0xffffffffu, slo, 1);
    slo += __shfl_xor_sync(0xffffffffu, slo, 2);
    shi += __shfl_xor_sync(0xffffffffu, shi, 1);
    shi += __shfl_xor_sync(0xffffffffu, shi, 2);
    const float ilo = 1.0f / slo, ihi = 1.0f / shi;

    uint32_t pf[7][2];
#pragma unroll
    for (int j = 0; j < 7; j++) {
        pf[j][0] = pack2h(__float2half_rn(sacc[j][0] * ilo),
                          __float2half_rn(sacc[j][1] * ilo));
        pf[j][1] = pack2h(__float2half_rn(sacc[j][2] * ihi),
                          __float2half_rn(sacc[j][3] * ihi));
    }

    float oacc[4][4];
#pragma unroll
    for (int nt = 0; nt < 4; nt++)
#pragma unroll
        for (int i = 0; i < 4; i++) oacc[nt][i] = 0.f;

    const int grp = lane >> 3, lr8 = lane & 7;
    const int vrow_off = lr8 + ((grp & 1) ? 8 : 0);
    const int vcol_off = (grp >= 2) ? 8 : 0;
#pragma unroll
    for (int kk = 0; kk < 4; kk++) {
        uint32_t a[4];
        a[0] = pf[2 * kk][0];
        a[1] = pf[2 * kk][1];
        a[2] = (2 * kk + 1 < 7) ? pf[2 * kk + 1][0] : 0u;
        a[3] = (2 * kk + 1 < 7) ? pf[2 * kk + 1][1] : 0u;
#pragma unroll
        for (int nv = 0; nv < 2; nv++) {
            uint32_t va = vb + ((kk * 16 + vrow_off) * ASTR + nv * 16 + vcol_off) * 2;
            uint32_t r0, r1, r2, r3;
            LDSM4T(r0, r1, r2, r3, va);
            uint32_t b0[2] = { r0, r1 };
            uint32_t b1[2] = { r2, r3 };
            MMA_FP16(oacc[2 * nv], a, b0);
            MMA_FP16(oacc[2 * nv + 1], a, b1);
        }
    }

    // ---- epilogue: rows m0+g, m0+g+8 -> g_att_h (fp16) ----
    const size_t obase = (size_t)(win * NTOK) * CCH + h * HD;
    if (r_lo < NTOK) {
        size_t rb = obase + (size_t)r_lo * CCH;
#pragma unroll
        for (int nt = 0; nt < 4; nt++) {
            int col = nt * 8 + 2 * t;
            *(uint32_t*)(g_att_h + rb + col) =
                pack2h(__float2half_rn(oacc[nt][0]), __float2half_rn(oacc[nt][1]));
        }
    }
    if (r_hi < NTOK) {
        size_t rb = obase + (size_t)r_hi * CCH;
#pragma unroll
        for (int nt = 0; nt < 4; nt++) {
            int col = nt * 8 + 2 * t;
            *(uint32_t*)(g_att_h + rb + col) =
                pack2h(__float2half_rn(oacc[nt][2]), __float2half_rn(oacc[nt][3]));
        }
    }
}

// ---------------------------------------------------------------------------
extern "C" void kernel_launch(void* const* d_in, const int* in_sizes, int n_in,
                              void* d_out, int out_size)
{
    const float* x      = (const float*)d_in[0];
    const float* qkv_w  = (const float*)d_in[1];
    const float* qkv_b  = (const float*)d_in[2];
    const float* proj_w = (const float*)d_in[3];
    const float* proj_b = (const float*)d_in[4];
    const float* rel    = (const float*)d_in[5];
    float* out = (float*)d_out;

    cudaFuncSetAttribute(gemm_mma_kernel<true>,
                         cudaFuncAttributeMaxDynamicSharedMemorySize, SMEM_DYN);
    cudaFuncSetAttribute(gemm_mma_kernel<false>,
                         cudaFuncAttributeMaxDynamicSharedMemorySize, SMEM_DYN);

    build_rowidx_kernel<<<(MROWS + 255) / 256, 256>>>();
    convert_w_kernel<<<(QKVC * CCH + 255) / 256, 256>>>(qkv_w, proj_w);
    convert_x_kernel<<<(int)(((size_t)MROWS * 128 + 255) / 256), 256>>>(x);

    // QKV: M=100352, N=1536 -> fp16 g_qkvh
    gemm_mma_kernel<true><<<dim3(QKVC / 128, MROWS / 128), 256, SMEM_DYN>>>(
        qkv_b, nullptr);

    attn_kernel<<<TOTWIN * NHEAD, 128>>>(rel);

    // proj: M=100352, N=512 (A = g_att_h, scatter-C to out)
    gemm_mma_kernel<false><<<dim3(CCH / 128, MROWS / 128), 256, SMEM_DYN>>>(
        proj_b, out);
}